// round 8
// baseline (speedup 1.0000x reference)
#include <cuda_runtime.h>
#include <cuda_bf16.h>
#include <math.h>

// ---------------- problem constants ----------------
#define B   32
#define LP  2048
#define LD  512
#define DP  1280
#define DD  768
#define GP  (LP/8)      // 256
#define GD  (LD/8)      // 64
#define HID 512
#define NH  8
#define HD  64
#define INFV 1e6f
#define EPS 1e-5f

// ---------------- device scratch (static; no allocs) ----------------
__device__ float d_pgE[B*GP*DP];       // grouped prot embed  [32,256,1280]
__device__ float d_dgE[B*GD*DD];       // grouped drug embed  [32,64,768]
__device__ float d_pg [B*GP*HID];
__device__ float d_dg [B*GD*HID];
__device__ float d_qkvp[3][B*GP*HID];  // q,k,v for prot
__device__ float d_qkvd[3][B*GD*HID];  // q,k,v for drug
__device__ float d_pe [B*GP*HID];
__device__ float d_de [B*GD*HID];
__device__ int   d_mp [B*GP];
__device__ int   d_md [B*GD];
__device__ float d_x  [B*1024];
__device__ float d_x1 [B*1024];
__device__ float d_x2 [B*512];
__device__ float d_x3 [B*256];
__device__ int   d_mask_layout;        // 0=int32, 1=uint8, 2=float32

// ---------------- mask layout detection ----------------
// bool masks: device dtype unknown (bool isn't a listed harness dtype).
// Random 0/1 data makes byte patterns unambiguous within 4KB:
//   int32:  nonzero bytes only at offset%4==0 (value 1)
//   uint8:  value-1 bytes at offsets %4 != 0
//   float32: 1.0f = 00 00 80 3F -> nonzero bytes at %4==2/3, never value 1
__global__ void detect_mask_kernel(const unsigned char* __restrict__ m) {
    int u8 = 0, f32 = 0;
    for (int i = 0; i < 4096; i++) {
        unsigned char v = m[i];
        int r = i & 3;
        if (r != 0 && v != 0) {
            if (v == 1) u8 = 1; else f32 = 1;
        }
    }
    d_mask_layout = u8 ? 1 : (f32 ? 2 : 0);
}

__device__ __forceinline__ int read_mask(const void* m, int idx, int layout) {
    if (layout == 0) return ((const int*)m)[idx] != 0;
    if (layout == 1) return ((const unsigned char*)m)[idx] != 0;
    return ((const float*)m)[idx] != 0.0f;
}

// ---------------- grouping (vectorized float4) ----------------
// Y[b,g,d] = mean_{r<8} X[b, g*8+r, d]; D % 4 == 0 guaranteed (1280 / 768).
__global__ void group_embed_kernel(const float4* __restrict__ X, float4* __restrict__ Y,
                                   int L, int D4) {
    long idx = (long)blockIdx.x * blockDim.x + threadIdx.x;   // in float4 units
    long total = (long)B * (L/8) * D4;
    if (idx >= total) return;
    int d   = (int)(idx % D4);
    long bg = idx / D4;
    int g  = (int)(bg % (L/8));
    int b  = (int)(bg / (L/8));
    const float4* p = X + ((long)b*L + (long)g*8) * D4 + d;
    float sx=0.f, sy=0.f, sz=0.f, sw=0.f;
    #pragma unroll
    for (int r = 0; r < 8; r++) {
        float4 v = p[(long)r*D4];
        sx += v.x; sy += v.y; sz += v.z; sw += v.w;
    }
    float4 o; o.x = sx*0.125f; o.y = sy*0.125f; o.z = sz*0.125f; o.w = sw*0.125f;
    Y[idx] = o;
}

__global__ void group_mask_kernel(const void* __restrict__ m, int* __restrict__ mg, int L) {
    int idx = blockIdx.x * blockDim.x + threadIdx.x;
    int G = L / 8;
    if (idx >= B * G) return;
    int g = idx % G, b = idx / G;
    int layout = d_mask_layout;
    int any = 0;
    #pragma unroll
    for (int r = 0; r < 8; r++) any |= read_mask(m, b*L + g*8 + r, layout);
    mg[idx] = any;
}

// ---------------- SGEMM: C[M,N] = A[M,K] @ W[K,N] (+bias) ----------------
// 128x128 block tile, K-step 8, 256 threads, 8x8 per-thread register tile.
// blockIdx.z selects among weight/output pairs (batched q/k/v).
// Requires M%128==0, N%128==0, K%8==0 (all shapes comply).
__global__ __launch_bounds__(256) void sgemm_bias_kernel(
    const float* __restrict__ A,
    const float* __restrict__ W0, const float* __restrict__ W1, const float* __restrict__ W2,
    const float* __restrict__ bias,
    float* __restrict__ C0, float* __restrict__ C1, float* __restrict__ C2,
    int M, int N, int K)
{
    const float* Wm = (blockIdx.z == 0) ? W0 : (blockIdx.z == 1) ? W1 : W2;
    float* C        = (blockIdx.z == 0) ? C0 : (blockIdx.z == 1) ? C1 : C2;

    __shared__ float As[8][128];
    __shared__ float Bs[8][128];
    const int tid = threadIdx.x;
    const int tx = tid & 15, ty = tid >> 4;

    const long arowg = (long)(blockIdx.y * 128 + (tid >> 1));
    const int  ac    = (tid & 1) * 4;
    const int  brow  = tid >> 5;
    const int  bc    = (tid & 31) * 4;
    const int  cb    = blockIdx.x * 128;

    float acc[8][8];
    #pragma unroll
    for (int i = 0; i < 8; i++)
        #pragma unroll
        for (int j = 0; j < 8; j++) acc[i][j] = 0.f;

    for (int k0 = 0; k0 < K; k0 += 8) {
        float4 av = *(const float4*)(A  + arowg * K + (k0 + ac));
        float4 bv = *(const float4*)(Wm + (long)(k0 + brow) * N + (cb + bc));
        __syncthreads();
        As[ac+0][tid>>1] = av.x; As[ac+1][tid>>1] = av.y;
        As[ac+2][tid>>1] = av.z; As[ac+3][tid>>1] = av.w;
        *(float4*)&Bs[brow][bc] = bv;
        __syncthreads();
        #pragma unroll
        for (int k = 0; k < 8; k++) {
            float4 a0 = *(const float4*)&As[k][ty*4];
            float4 a1 = *(const float4*)&As[k][64 + ty*4];
            float4 b0 = *(const float4*)&Bs[k][tx*4];
            float4 b1 = *(const float4*)&Bs[k][64 + tx*4];
            float a[8] = {a0.x,a0.y,a0.z,a0.w,a1.x,a1.y,a1.z,a1.w};
            float bb[8] = {b0.x,b0.y,b0.z,b0.w,b1.x,b1.y,b1.z,b1.w};
            #pragma unroll
            for (int i = 0; i < 8; i++)
                #pragma unroll
                for (int j = 0; j < 8; j++) acc[i][j] += a[i] * bb[j];
        }
    }

    // bias values for this thread's two column groups, loaded once
    float4 bias0 = make_float4(0.f,0.f,0.f,0.f), bias1 = bias0;
    if (bias) {
        bias0 = *(const float4*)&bias[cb + tx*4];
        bias1 = *(const float4*)&bias[cb + 64 + tx*4];
    }

    const int rb = blockIdx.y * 128;
    #pragma unroll
    for (int ih = 0; ih < 2; ih++) {
        #pragma unroll
        for (int i = 0; i < 4; i++) {
            int r = rb + ih*64 + ty*4 + i;
            #pragma unroll
            for (int jh = 0; jh < 2; jh++) {
                int c = cb + jh*64 + tx*4;
                float4 bvals = jh ? bias1 : bias0;
                float4 o;
                o.x = acc[ih*4+i][jh*4+0] + bvals.x;
                o.y = acc[ih*4+i][jh*4+1] + bvals.y;
                o.z = acc[ih*4+i][jh*4+2] + bvals.z;
                o.w = acc[ih*4+i][jh*4+3] + bvals.w;
                *(float4*)&C[(long)r * N + c] = o;
            }
        }
    }
}

// ---------------- fused masked attention (online softmax) ----------------
// out[b,i,h,:] (init ? = : +=) 0.5 * softmax_j(masked q_i.k_j) @ V
// One warp per query row; 8 warps/block; K/V staged in smem chunks of 32 rows.
__global__ __launch_bounds__(256) void attn_kernel(
    const float* __restrict__ Q, const float* __restrict__ Kt,
    const float* __restrict__ V,
    const int* __restrict__ mrow, const int* __restrict__ mcol,
    float* __restrict__ out, int Gq, int Gk, int init)
{
    const int b = blockIdx.z, h = blockIdx.y;
    const int warp = threadIdx.x >> 5, lane = threadIdx.x & 31;
    const int i = blockIdx.x * 8 + warp;

    __shared__ float Qs[8][68];
    __shared__ float Ks[32][68];
    __shared__ float Vs[32][66];
    __shared__ int   mcs[32];

    if (threadIdx.x < 128) {
        int r = threadIdx.x >> 4, c4 = (threadIdx.x & 15) * 4;
        const float* qp = Q + ((long)(b*Gq + blockIdx.x*8 + r) * HID) + h*HD + c4;
        float4 v = *(const float4*)qp;
        Qs[r][c4] = v.x; Qs[r][c4+1] = v.y; Qs[r][c4+2] = v.z; Qs[r][c4+3] = v.w;
    }
    const int mr = mrow[b*Gq + i];

    float mmax = -1e30f, lsum = 0.f, acc0 = 0.f, acc1 = 0.f;

    for (int j0 = 0; j0 < Gk; j0 += 32) {
        __syncthreads();
        for (int t = threadIdx.x; t < 512; t += 256) {
            int r = t >> 4, c4 = (t & 15) * 4;
            long base = ((long)(b*Gk + j0 + r) * HID) + h*HD + c4;
            float4 kv = *(const float4*)(Kt + base);
            Ks[r][c4] = kv.x; Ks[r][c4+1] = kv.y; Ks[r][c4+2] = kv.z; Ks[r][c4+3] = kv.w;
            float4 vv = *(const float4*)(V + base);
            Vs[r][c4] = vv.x; Vs[r][c4+1] = vv.y; Vs[r][c4+2] = vv.z; Vs[r][c4+3] = vv.w;
        }
        if (threadIdx.x < 32) mcs[threadIdx.x] = mcol[b*Gk + j0 + threadIdx.x];
        __syncthreads();

        // logit for key j = j0 + lane
        float logit = 0.f;
        #pragma unroll
        for (int d4 = 0; d4 < HD; d4 += 4) {
            float4 qv = *(const float4*)&Qs[warp][d4];
            float4 kv = *(const float4*)&Ks[lane][d4];
            logit += qv.x*kv.x + qv.y*kv.y + qv.z*kv.z + qv.w*kv.w;
        }
        if (!(mr && mcs[lane])) logit -= INFV;   // exact reference semantics

        float cm = logit;
        #pragma unroll
        for (int o = 16; o; o >>= 1) cm = fmaxf(cm, __shfl_xor_sync(0xffffffffu, cm, o));
        float mnew  = fmaxf(mmax, cm);
        float scale = __expf(mmax - mnew);
        float p     = __expf(logit - mnew);
        float ps = p;
        #pragma unroll
        for (int o = 16; o; o >>= 1) ps += __shfl_xor_sync(0xffffffffu, ps, o);
        lsum = lsum * scale + ps;
        acc0 *= scale; acc1 *= scale;
        mmax = mnew;

        // accumulate P@V, 4 keys per step to batch shfl latency
        #pragma unroll
        for (int jj = 0; jj < 32; jj += 4) {
            float p0 = __shfl_sync(0xffffffffu, p, jj+0);
            float p1 = __shfl_sync(0xffffffffu, p, jj+1);
            float p2 = __shfl_sync(0xffffffffu, p, jj+2);
            float p3 = __shfl_sync(0xffffffffu, p, jj+3);
            float2 v0 = *(const float2*)&Vs[jj+0][lane*2];
            float2 v1 = *(const float2*)&Vs[jj+1][lane*2];
            float2 v2 = *(const float2*)&Vs[jj+2][lane*2];
            float2 v3 = *(const float2*)&Vs[jj+3][lane*2];
            acc0 += p0*v0.x + p1*v1.x + p2*v2.x + p3*v3.x;
            acc1 += p0*v0.y + p1*v1.y + p2*v2.y + p3*v3.y;
        }
    }

    float inv = 1.f / lsum;
    float o0 = mr ? acc0 * inv * 0.5f : 0.f;
    float o1 = mr ? acc1 * inv * 0.5f : 0.f;
    float* op = out + ((long)(b*Gq + i) * HID) + h*HD + lane*2;
    if (init) { op[0] = o0;  op[1] = o1; }
    else      { op[0] += o0; op[1] += o1; }
}

// ---------------- masked mean pooling + concat ----------------
__global__ void pool_kernel(const float* __restrict__ pe, const float* __restrict__ de,
                            const int* __restrict__ mp, const int* __restrict__ md,
                            float* __restrict__ x)
{
    int b = blockIdx.x, d = threadIdx.x;   // 512 threads
    float cp = 0.f, sp = 0.f;
    for (int g = 0; g < GP; g++) {
        float m = (float)mp[b*GP + g];
        cp += m;
        sp += m * pe[((long)b*GP + g) * HID + d];
    }
    x[b*1024 + d] = sp / cp;
    float cd = 0.f, sd = 0.f;
    for (int g = 0; g < GD; g++) {
        float m = (float)md[b*GD + g];
        cd += m;
        sd += m * de[((long)b*GD + g) * HID + d];
    }
    x[b*1024 + 512 + d] = sd / cd;
}

// ---------------- MLP layer: relu(X@W+b) then train-mode BN over batch ----------------
__global__ void mlp_layer_kernel(const float* __restrict__ X, const float* __restrict__ Wm,
                                 const float* __restrict__ bias, const float* __restrict__ gamma,
                                 const float* __restrict__ beta, float* __restrict__ Y,
                                 int Kdim, int N)
{
    int n = blockIdx.x, b = threadIdx.x;   // 32 threads (one warp)
    float s = bias[n];
    for (int k = 0; k < Kdim; k++) s += X[b*Kdim + k] * Wm[(long)k*N + n];
    s = fmaxf(s, 0.f);
    float mu = s;
    #pragma unroll
    for (int o = 16; o; o >>= 1) mu += __shfl_xor_sync(0xffffffffu, mu, o);
    mu *= (1.f/32.f);
    float diff = s - mu;
    float var = diff * diff;
    #pragma unroll
    for (int o = 16; o; o >>= 1) var += __shfl_xor_sync(0xffffffffu, var, o);
    var *= (1.f/32.f);
    Y[b*N + n] = gamma[n] * diff * rsqrtf(var + EPS) + beta[n];
}

// ---------------- final: sigmoid(x3 @ wo + bo) ----------------
__global__ void final_kernel(const float* __restrict__ X3, const float* __restrict__ wo,
                             const float* __restrict__ bo, float* __restrict__ out)
{
    int b = blockIdx.x, t = threadIdx.x;   // 256 threads
    __shared__ float red[256];
    red[t] = X3[b*256 + t] * wo[t];
    __syncthreads();
    for (int st = 128; st; st >>= 1) {
        if (t < st) red[t] += red[t + st];
        __syncthreads();
    }
    if (t == 0) out[b] = 1.f / (1.f + __expf(-(red[0] + bo[0])));
}

// ---------------- launch ----------------
static void* sym(const void* s) { void* p = nullptr; cudaGetSymbolAddress(&p, s); return p; }

extern "C" void kernel_launch(void* const* d_in, const int* in_sizes, int n_in,
                              void* d_out, int out_size)
{
    const float* prot_embed = (const float*)d_in[0];
    const float* drug_embed = (const float*)d_in[1];
    const void*  prot_mask  = d_in[2];
    const void*  drug_mask  = d_in[3];
    const float* w_preg = (const float*)d_in[4];
    const float* b_preg = (const float*)d_in[5];
    const float* w_dreg = (const float*)d_in[6];
    const float* b_dreg = (const float*)d_in[7];
    const float* wqp = (const float*)d_in[8];
    const float* wkp = (const float*)d_in[9];
    const float* wvp = (const float*)d_in[10];
    const float* wqd = (const float*)d_in[11];
    const float* wkd = (const float*)d_in[12];
    const float* wvd = (const float*)d_in[13];
    const float* w1  = (const float*)d_in[14];
    const float* b1  = (const float*)d_in[15];
    const float* g1  = (const float*)d_in[16];
    const float* be1 = (const float*)d_in[17];
    const float* w2  = (const float*)d_in[18];
    const float* b2  = (const float*)d_in[19];
    const float* g2  = (const float*)d_in[20];
    const float* be2 = (const float*)d_in[21];
    const float* w3  = (const float*)d_in[22];
    const float* b3  = (const float*)d_in[23];
    const float* g3  = (const float*)d_in[24];
    const float* be3 = (const float*)d_in[25];
    const float* wo  = (const float*)d_in[26];
    const float* bo  = (const float*)d_in[27];

    float* pgE = (float*)sym(d_pgE);
    float* dgE = (float*)sym(d_dgE);
    float* pg  = (float*)sym(d_pg);
    float* dg  = (float*)sym(d_dg);
    float* qkvp = (float*)sym(d_qkvp);
    float* qkvd = (float*)sym(d_qkvd);
    float* qp = qkvp;                 float* kp = qkvp + (long)B*GP*HID; float* vp = qkvp + 2L*B*GP*HID;
    float* qd = qkvd;                 float* kd = qkvd + (long)B*GD*HID; float* vd = qkvd + 2L*B*GD*HID;
    float* pe  = (float*)sym(d_pe);
    float* de  = (float*)sym(d_de);
    int*   mp  = (int*)  sym(d_mp);
    int*   md  = (int*)  sym(d_md);
    float* x   = (float*)sym(d_x);
    float* x1  = (float*)sym(d_x1);
    float* x2  = (float*)sym(d_x2);
    float* x3  = (float*)sym(d_x3);
    float* out = (float*)d_out;

    // 0. classify mask dtype layout (deterministic given inputs)
    detect_mask_kernel<<<1, 1>>>((const unsigned char*)prot_mask);

    // 1. group embeddings (projection commutes with group-mean: 8x FLOP cut)
    {
        long tp = (long)B*GP*(DP/4);
        group_embed_kernel<<<(int)((tp + 255)/256), 256>>>((const float4*)prot_embed, (float4*)pgE, LP, DP/4);
        long td = (long)B*GD*(DD/4);
        group_embed_kernel<<<(int)((td + 255)/256), 256>>>((const float4*)drug_embed, (float4*)dgE, LD, DD/4);
        group_mask_kernel<<<(B*GP + 255)/256, 256>>>(prot_mask, mp, LP);
        group_mask_kernel<<<(B*GD + 255)/256, 256>>>(drug_mask, md, LD);
    }

    // 2. regression projections
    sgemm_bias_kernel<<<dim3(HID/128, (B*GP)/128, 1), 256>>>(pgE, w_preg, w_preg, w_preg, b_preg, pg, pg, pg, B*GP, HID, DP);
    sgemm_bias_kernel<<<dim3(HID/128, (B*GD)/128, 1), 256>>>(dgE, w_dreg, w_dreg, w_dreg, b_dreg, dg, dg, dg, B*GD, HID, DD);

    // 3. q/k/v projections (no bias), batched over blockIdx.z
    sgemm_bias_kernel<<<dim3(HID/128, (B*GP)/128, 3), 256>>>(pg, wqp, wkp, wvp, nullptr, qp, kp, vp, B*GP, HID, HID);
    sgemm_bias_kernel<<<dim3(HID/128, (B*GD)/128, 3), 256>>>(dg, wqd, wkd, wvd, nullptr, qd, kd, vd, B*GD, HID, HID);

    // 4. cross attention: pe = 0.5*(attn(qp,kp,vp) + attn(qp,kd,vd)); de symmetric
    attn_kernel<<<dim3(GP/8, NH, B), 256>>>(qp, kp, vp, mp, mp, pe, GP, GP, 1);
    attn_kernel<<<dim3(GP/8, NH, B), 256>>>(qp, kd, vd, mp, md, pe, GP, GD, 0);
    attn_kernel<<<dim3(GD/8, NH, B), 256>>>(qd, kp, vp, md, mp, de, GD, GP, 1);
    attn_kernel<<<dim3(GD/8, NH, B), 256>>>(qd, kd, vd, md, md, de, GD, GD, 0);

    // 5. masked-mean pooling + concat -> x [32, 1024]
    pool_kernel<<<B, 512>>>(pe, de, mp, md, x);

    // 6. MLP decoder with train-mode BatchNorm
    mlp_layer_kernel<<<1024, 32>>>(x,  w1, b1, g1, be1, x1, 1024, 1024);
    mlp_layer_kernel<<<512,  32>>>(x1, w2, b2, g2, be2, x2, 1024, 512);
    mlp_layer_kernel<<<256,  32>>>(x2, w3, b3, g3, be3, x3, 512,  256);

    // 7. output head
    final_kernel<<<B, 256>>>(x3, wo, bo, out);

    (void)in_sizes; (void)n_in; (void)out_size;
}

// round 11
// speedup vs baseline: 1.6537x; 1.6537x over previous
#include <cuda_runtime.h>
#include <cuda_bf16.h>
#include <mma.h>
#include <math.h>
#include <stdint.h>

using namespace nvcuda;

// ---------------- problem constants ----------------
#define B   32
#define LP  2048
#define LD  512
#define DP  1280
#define DD  768
#define GP  (LP/8)      // 256
#define GD  (LD/8)      // 64
#define HID 512
#define NH  8
#define HD  64
#define INFV 1e6f
#define EPS 1e-5f

// ---------------- device scratch (static; no allocs) ----------------
__device__ __nv_bfloat16 d_pgEh[B*GP*DP], d_pgEl[B*GP*DP];     // grouped prot embed (hi/lo)
__device__ __nv_bfloat16 d_dgEh[B*GD*DD], d_dgEl[B*GD*DD];     // grouped drug embed (hi/lo)
__device__ __nv_bfloat16 d_pgh [B*GP*HID], d_pgl [B*GP*HID];   // proj prot (split)
__device__ __nv_bfloat16 d_dgh [B*GD*HID], d_dgl [B*GD*HID];   // proj drug (split)
__device__ __nv_bfloat16 d_wpt_h[HID*DP],  d_wpt_l[HID*DP];    // w_preg^T  [512,1280]
__device__ __nv_bfloat16 d_wdt_h[HID*DD],  d_wdt_l[HID*DD];    // w_dreg^T  [512,768]
__device__ __nv_bfloat16 d_wqp_t[2][3][HID*HID];               // [hi/lo][q,k,v] prot W^T
__device__ __nv_bfloat16 d_wqd_t[2][3][HID*HID];               // [hi/lo][q,k,v] drug W^T
__device__ float d_qkvp[3][B*GP*HID];
__device__ float d_qkvd[3][B*GD*HID];
__device__ float d_pe [B*GP*HID];
__device__ float d_de [B*GD*HID];
__device__ int   d_mp [B*GP];
__device__ int   d_md [B*GD];
__device__ float d_x  [B*1024];
__device__ float d_x1 [B*1024];
__device__ float d_x2 [B*512];
__device__ float d_x3 [B*256];
__device__ int   d_mask_layout;

// ---------------- small helpers ----------------
__device__ __forceinline__ void bsplit(float x, __nv_bfloat16& h, __nv_bfloat16& l) {
    h = __float2bfloat16(x);
    l = __float2bfloat16(x - __bfloat162float(h));
}

// ---------------- mask layout detection (validated R8) ----------------
__global__ void detect_mask_kernel(const unsigned char* __restrict__ m) {
    int u8 = 0, f32 = 0;
    for (int i = 0; i < 4096; i++) {
        unsigned char v = m[i];
        int r = i & 3;
        if (r != 0 && v != 0) {
            if (v == 1) u8 = 1; else f32 = 1;
        }
    }
    d_mask_layout = u8 ? 1 : (f32 ? 2 : 0);
}

__device__ __forceinline__ int read_mask(const void* m, int idx, int layout) {
    if (layout == 0) return ((const int*)m)[idx] != 0;
    if (layout == 1) return ((const unsigned char*)m)[idx] != 0;
    return ((const float*)m)[idx] != 0.0f;
}

// ---------------- grouping: mean over 8 rows -> bf16 hi/lo split ----------------
__global__ void group_embed_split_kernel(const float4* __restrict__ X,
                                         __nv_bfloat16* __restrict__ Yh,
                                         __nv_bfloat16* __restrict__ Yl,
                                         int L, int D4) {
    long idx = (long)blockIdx.x * blockDim.x + threadIdx.x;   // float4 units
    long total = (long)B * (L/8) * D4;
    if (idx >= total) return;
    int d   = (int)(idx % D4);
    long bg = idx / D4;
    int g  = (int)(bg % (L/8));
    int b  = (int)(bg / (L/8));
    const float4* p = X + ((long)b*L + (long)g*8) * D4 + d;
    float sx=0.f, sy=0.f, sz=0.f, sw=0.f;
    #pragma unroll
    for (int r = 0; r < 8; r++) {
        float4 v = p[(long)r*D4];
        sx += v.x; sy += v.y; sz += v.z; sw += v.w;
    }
    __nv_bfloat16 h0,l0,h1,l1,h2,l2,h3,l3;
    bsplit(sx*0.125f, h0, l0); bsplit(sy*0.125f, h1, l1);
    bsplit(sz*0.125f, h2, l2); bsplit(sw*0.125f, h3, l3);
    __nv_bfloat162* yh = (__nv_bfloat162*)Yh;
    __nv_bfloat162* yl = (__nv_bfloat162*)Yl;
    yh[idx*2+0] = __nv_bfloat162(h0, h1); yh[idx*2+1] = __nv_bfloat162(h2, h3);
    yl[idx*2+0] = __nv_bfloat162(l0, l1); yl[idx*2+1] = __nv_bfloat162(l2, l3);
}

__global__ void group_mask_kernel(const void* __restrict__ m, int* __restrict__ mg, int L) {
    int idx = blockIdx.x * blockDim.x + threadIdx.x;
    int G = L / 8;
    if (idx >= B * G) return;
    int g = idx % G, b = idx / G;
    int layout = d_mask_layout;
    int any = 0;
    #pragma unroll
    for (int r = 0; r < 8; r++) any |= read_mask(m, b*L + g*8 + r, layout);
    mg[idx] = any;
}

// ---------------- weight transpose + bf16 split: W[K,512] -> T[512,K] hi/lo ----------------
__global__ void transpose_split_kernel(const float* __restrict__ W,
                                       __nv_bfloat16* __restrict__ Th,
                                       __nv_bfloat16* __restrict__ Tl, int K) {
    long idx = (long)blockIdx.x * blockDim.x + threadIdx.x;   // over N*K, K-major out
    if (idx >= (long)HID * K) return;
    int k = (int)(idx % K), n = (int)(idx / K);
    float v = W[(long)k * HID + n];
    __nv_bfloat16 h, l; bsplit(v, h, l);
    Th[idx] = h; Tl[idx] = l;
}

// ---------------- bias add + bf16 split (proj epilogue) ----------------
__global__ void bias_split_kernel(const float* __restrict__ C, const float* __restrict__ bias,
                                  __nv_bfloat16* __restrict__ Yh, __nv_bfloat16* __restrict__ Yl,
                                  long total) {
    long idx = (long)blockIdx.x * blockDim.x + threadIdx.x;
    if (idx >= total) return;
    float v = C[idx] + bias[idx & (HID-1)];
    __nv_bfloat16 h, l; bsplit(v, h, l);
    Yh[idx] = h; Yl[idx] = l;
}

// ---------------- wmma GEMM: C[M,512] = A[M,K] @ T[512,K]^T ----------------
// Compensated bf16: C = Ah*Bh + Al*Bh + Ah*Bl  (fp32-grade accuracy, fp32 accum).
// 128x128 CTA tile; 8 warps; warp tile 32x64 (2x4 wmma 16x16x16 frags).
// A row-major [M,K]; W^T stored [N,K] == B col-major with ldm = tile K-pad.
// blockIdx.z selects among up to 3 weight/output sets (batched q/k/v).
#define GT_PAD 40                        // 32 K-chunk + 8 pad (ldm mult of 8)
__global__ __launch_bounds__(256) void gemm_wmma_kernel(
    const __nv_bfloat16* __restrict__ Ahi, const __nv_bfloat16* __restrict__ Alo,
    const __nv_bfloat16* __restrict__ Wh0, const __nv_bfloat16* __restrict__ Wh1,
    const __nv_bfloat16* __restrict__ Wh2,
    const __nv_bfloat16* __restrict__ Wl0, const __nv_bfloat16* __restrict__ Wl1,
    const __nv_bfloat16* __restrict__ Wl2,
    float* __restrict__ C0, float* __restrict__ C1, float* __restrict__ C2,
    int K)
{
    const __nv_bfloat16* Wh = (blockIdx.z == 0) ? Wh0 : (blockIdx.z == 1) ? Wh1 : Wh2;
    const __nv_bfloat16* Wl = (blockIdx.z == 0) ? Wl0 : (blockIdx.z == 1) ? Wl1 : Wl2;
    float* C                = (blockIdx.z == 0) ? C0  : (blockIdx.z == 1) ? C1  : C2;

    __shared__ __nv_bfloat16 sAh[128*GT_PAD], sAl[128*GT_PAD];
    __shared__ __nv_bfloat16 sBh[128*GT_PAD], sBl[128*GT_PAD];

    const int tid  = threadIdx.x;
    const int warp = tid >> 5;
    const int wm   = warp & 3;           // 4 M-warps x 32 rows
    const int wn   = warp >> 2;          // 2 N-warps x 64 cols
    const int rowBase = blockIdx.y * 128, nBase = blockIdx.x * 128;

    wmma::fragment<wmma::accumulator, 16, 16, 16, float> acc[2][4];
    #pragma unroll
    for (int mi = 0; mi < 2; mi++)
        #pragma unroll
        for (int ni = 0; ni < 4; ni++) wmma::fill_fragment(acc[mi][ni], 0.f);

    for (int k0 = 0; k0 < K; k0 += 32) {
        __syncthreads();
        // stage 128x32 of each operand (hi+lo); uint4 = 8 bf16
        for (int u = tid; u < 512; u += 256) {
            int r = u >> 2, c8 = u & 3;
            long ga = (long)(rowBase + r) * K + k0 + c8*8;
            long gb = (long)(nBase   + r) * K + k0 + c8*8;
            int so = r*GT_PAD + c8*8;
            *(uint4*)&sAh[so] = *(const uint4*)(Ahi + ga);
            *(uint4*)&sAl[so] = *(const uint4*)(Alo + ga);
            *(uint4*)&sBh[so] = *(const uint4*)(Wh  + gb);
            *(uint4*)&sBl[so] = *(const uint4*)(Wl  + gb);
        }
        __syncthreads();

        #pragma unroll
        for (int ks = 0; ks < 2; ks++) {
            wmma::fragment<wmma::matrix_a, 16, 16, 16, __nv_bfloat16, wmma::row_major> a_h[2], a_l[2];
            wmma::fragment<wmma::matrix_b, 16, 16, 16, __nv_bfloat16, wmma::col_major> b_h[4], b_l[4];
            #pragma unroll
            for (int mi = 0; mi < 2; mi++) {
                int r = (wm*32 + mi*16) * GT_PAD + ks*16;
                wmma::load_matrix_sync(a_h[mi], &sAh[r], GT_PAD);
                wmma::load_matrix_sync(a_l[mi], &sAl[r], GT_PAD);
            }
            #pragma unroll
            for (int ni = 0; ni < 4; ni++) {
                int r = (wn*64 + ni*16) * GT_PAD + ks*16;
                wmma::load_matrix_sync(b_h[ni], &sBh[r], GT_PAD);
                wmma::load_matrix_sync(b_l[ni], &sBl[r], GT_PAD);
            }
            #pragma unroll
            for (int mi = 0; mi < 2; mi++)
                #pragma unroll
                for (int ni = 0; ni < 4; ni++) {
                    wmma::mma_sync(acc[mi][ni], a_h[mi], b_h[ni], acc[mi][ni]);
                    wmma::mma_sync(acc[mi][ni], a_l[mi], b_h[ni], acc[mi][ni]);
                    wmma::mma_sync(acc[mi][ni], a_h[mi], b_l[ni], acc[mi][ni]);
                }
        }
    }

    #pragma unroll
    for (int mi = 0; mi < 2; mi++)
        #pragma unroll
        for (int ni = 0; ni < 4; ni++) {
            long off = (long)(rowBase + wm*32 + mi*16) * HID + nBase + wn*64 + ni*16;
            wmma::store_matrix_sync(C + off, acc[mi][ni], HID, wmma::mem_row_major);
        }
}

// ---------------- fused masked attention: 4 query rows / warp, 32 rows / block ----------------
__global__ __launch_bounds__(256) void attn_kernel(
    const float* __restrict__ Q, const float* __restrict__ Kt,
    const float* __restrict__ V,
    const int* __restrict__ mrow, const int* __restrict__ mcol,
    float* __restrict__ out, int Gq, int Gk, int init)
{
    const int b = blockIdx.z, h = blockIdx.y;
    const int warp = threadIdx.x >> 5, lane = threadIdx.x & 31;
    const int qtile = blockIdx.x * 32;
    const int r0 = warp * 4;

    __shared__ float Qs[32][68];
    __shared__ float Ks[32][68];
    __shared__ float Vs[32][68];
    __shared__ int   mcs[32];

    for (int t = threadIdx.x; t < 512; t += 256) {
        int r = t >> 4, c4 = (t & 15) * 4;
        *(float4*)&Qs[r][c4] = *(const float4*)(Q + ((long)(b*Gq + qtile + r) * HID) + h*HD + c4);
    }
    int mr[4];
    #pragma unroll
    for (int r = 0; r < 4; r++) mr[r] = mrow[b*Gq + qtile + r0 + r];

    float mmax[4], lsum[4], a0[4], a1[4];
    #pragma unroll
    for (int r = 0; r < 4; r++) { mmax[r] = -1e30f; lsum[r] = 0.f; a0[r] = 0.f; a1[r] = 0.f; }

    for (int j0 = 0; j0 < Gk; j0 += 32) {
        __syncthreads();
        for (int t = threadIdx.x; t < 512; t += 256) {
            int r = t >> 4, c4 = (t & 15) * 4;
            long base = ((long)(b*Gk + j0 + r) * HID) + h*HD + c4;
            *(float4*)&Ks[r][c4] = *(const float4*)(Kt + base);
            *(float4*)&Vs[r][c4] = *(const float4*)(V  + base);
        }
        if (threadIdx.x < 32) mcs[threadIdx.x] = mcol[b*Gk + j0 + threadIdx.x];
        __syncthreads();

        float lg[4] = {0.f, 0.f, 0.f, 0.f};
        #pragma unroll
        for (int d4 = 0; d4 < HD; d4 += 4) {
            float4 kv = *(const float4*)&Ks[lane][d4];
            #pragma unroll
            for (int r = 0; r < 4; r++) {
                float4 qv = *(const float4*)&Qs[r0 + r][d4];
                lg[r] += qv.x*kv.x + qv.y*kv.y + qv.z*kv.z + qv.w*kv.w;
            }
        }
        const int mc = mcs[lane];
        float pr[4];
        #pragma unroll
        for (int r = 0; r < 4; r++) {
            float logit = (mr[r] && mc) ? lg[r] : lg[r] - INFV;   // exact reference semantics
            float cm = logit;
            #pragma unroll
            for (int o = 16; o; o >>= 1) cm = fmaxf(cm, __shfl_xor_sync(0xffffffffu, cm, o));
            float mnew  = fmaxf(mmax[r], cm);
            float sc    = __expf(mmax[r] - mnew);
            pr[r]       = __expf(logit - mnew);
            float ps = pr[r];
            #pragma unroll
            for (int o = 16; o; o >>= 1) ps += __shfl_xor_sync(0xffffffffu, ps, o);
            lsum[r] = lsum[r]*sc + ps;
            a0[r] *= sc; a1[r] *= sc;
            mmax[r] = mnew;
        }
        #pragma unroll
        for (int jj = 0; jj < 32; jj += 2) {
            float2 v0 = *(const float2*)&Vs[jj+0][lane*2];
            float2 v1 = *(const float2*)&Vs[jj+1][lane*2];
            #pragma unroll
            for (int r = 0; r < 4; r++) {
                float p0 = __shfl_sync(0xffffffffu, pr[r], jj+0);
                float p1 = __shfl_sync(0xffffffffu, pr[r], jj+1);
                a0[r] += p0*v0.x + p1*v1.x;
                a1[r] += p0*v0.y + p1*v1.y;
            }
        }
    }

    #pragma unroll
    for (int r = 0; r < 4; r++) {
        float inv = 1.f / lsum[r];
        float o0 = mr[r] ? a0[r] * inv * 0.5f : 0.f;
        float o1 = mr[r] ? a1[r] * inv * 0.5f : 0.f;
        float* op = out + ((long)(b*Gq + qtile + r0 + r) * HID) + h*HD + lane*2;
        if (init) { op[0] = o0;  op[1] = o1; }
        else      { op[0] += o0; op[1] += o1; }
    }
}

// ---------------- masked mean pooling + concat ----------------
__global__ void pool_kernel(const float* __restrict__ pe, const float* __restrict__ de,
                            const int* __restrict__ mp, const int* __restrict__ md,
                            float* __restrict__ x)
{
    int b = blockIdx.x, d = threadIdx.x;   // 512 threads
    float cp = 0.f, sp = 0.f;
    for (int g = 0; g < GP; g++) {
        float m = (float)mp[b*GP + g];
        cp += m;
        sp += m * pe[((long)b*GP + g) * HID + d];
    }
    x[b*1024 + d] = sp / cp;
    float cd = 0.f, sd = 0.f;
    for (int g = 0; g < GD; g++) {
        float m = (float)md[b*GD + g];
        cd += m;
        sd += m * de[((long)b*GD + g) * HID + d];
    }
    x[b*1024 + 512 + d] = sd / cd;
}

// ---------------- MLP layer: relu(X@W+b) then train-mode BN over batch ----------------
__global__ void mlp_layer_kernel(const float* __restrict__ X, const float* __restrict__ Wm,
                                 const float* __restrict__ bias, const float* __restrict__ gamma,
                                 const float* __restrict__ beta, float* __restrict__ Y,
                                 int Kdim, int N)
{
    int n = blockIdx.x, b = threadIdx.x;   // 32 threads (one warp)
    float s = bias[n];
    for (int k = 0; k < Kdim; k++) s += X[b*Kdim + k] * Wm[(long)k*N + n];
    s = fmaxf(s, 0.f);
    float mu = s;
    #pragma unroll
    for (int o = 16; o; o >>= 1) mu += __shfl_xor_sync(0xffffffffu, mu, o);
    mu *= (1.f/32.f);
    float diff = s - mu;
    float var = diff * diff;
    #pragma unroll
    for (int o = 16; o; o >>= 1) var += __shfl_xor_sync(0xffffffffu, var, o);
    var *= (1.f/32.f);
    Y[b*N + n] = gamma[n] * diff * rsqrtf(var + EPS) + beta[n];
}

// ---------------- final: sigmoid(x3 @ wo + bo) ----------------
__global__ void final_kernel(const float* __restrict__ X3, const float* __restrict__ wo,
                             const float* __restrict__ bo, float* __restrict__ out)
{
    int b = blockIdx.x, t = threadIdx.x;   // 256 threads
    __shared__ float red[256];
    red[t] = X3[b*256 + t] * wo[t];
    __syncthreads();
    for (int st = 128; st; st >>= 1) {
        if (t < st) red[t] += red[t + st];
        __syncthreads();
    }
    if (t == 0) out[b] = 1.f / (1.f + __expf(-(red[0] + bo[0])));
}

// ---------------- launch ----------------
static void* sym(const void* s) { void* p = nullptr; cudaGetSymbolAddress(&p, s); return p; }

extern "C" void kernel_launch(void* const* d_in, const int* in_sizes, int n_in,
                              void* d_out, int out_size)
{
    const float* prot_embed = (const float*)d_in[0];
    const float* drug_embed = (const float*)d_in[1];
    const void*  prot_mask  = d_in[2];
    const void*  drug_mask  = d_in[3];
    const float* w_preg = (const float*)d_in[4];
    const float* b_preg = (const float*)d_in[5];
    const float* w_dreg = (const float*)d_in[6];
    const float* b_dreg = (const float*)d_in[7];
    const float* wqp = (const float*)d_in[8];
    const float* wkp = (const float*)d_in[9];
    const float* wvp = (const float*)d_in[10];
    const float* wqd = (const float*)d_in[11];
    const float* wkd = (const float*)d_in[12];
    const float* wvd = (const float*)d_in[13];
    const float* w1  = (const float*)d_in[14];
    const float* b1  = (const float*)d_in[15];
    const float* g1  = (const float*)d_in[16];
    const float* be1 = (const float*)d_in[17];
    const float* w2  = (const float*)d_in[18];
    const float* b2  = (const float*)d_in[19];
    const float* g2  = (const float*)d_in[20];
    const float* be2 = (const float*)d_in[21];
    const float* w3  = (const float*)d_in[22];
    const float* b3  = (const float*)d_in[23];
    const float* g3  = (const float*)d_in[24];
    const float* be3 = (const float*)d_in[25];
    const float* wo  = (const float*)d_in[26];
    const float* bo  = (const float*)d_in[27];

    __nv_bfloat16* pgEh = (__nv_bfloat16*)sym(d_pgEh);
    __nv_bfloat16* pgEl = (__nv_bfloat16*)sym(d_pgEl);
    __nv_bfloat16* dgEh = (__nv_bfloat16*)sym(d_dgEh);
    __nv_bfloat16* dgEl = (__nv_bfloat16*)sym(d_dgEl);
    __nv_bfloat16* pgh  = (__nv_bfloat16*)sym(d_pgh);
    __nv_bfloat16* pgl  = (__nv_bfloat16*)sym(d_pgl);
    __nv_bfloat16* dgh  = (__nv_bfloat16*)sym(d_dgh);
    __nv_bfloat16* dgl  = (__nv_bfloat16*)sym(d_dgl);
    __nv_bfloat16* wpt_h = (__nv_bfloat16*)sym(d_wpt_h);
    __nv_bfloat16* wpt_l = (__nv_bfloat16*)sym(d_wpt_l);
    __nv_bfloat16* wdt_h = (__nv_bfloat16*)sym(d_wdt_h);
    __nv_bfloat16* wdt_l = (__nv_bfloat16*)sym(d_wdt_l);
    __nv_bfloat16* wqpt  = (__nv_bfloat16*)sym(d_wqp_t);   // [2][3][HID*HID]
    __nv_bfloat16* wqdt  = (__nv_bfloat16*)sym(d_wqd_t);
    float* qkvp = (float*)sym(d_qkvp);
    float* qkvd = (float*)sym(d_qkvd);
    float* qp = qkvp;  float* kp = qkvp + (long)B*GP*HID;  float* vp = qkvp + 2L*B*GP*HID;
    float* qd = qkvd;  float* kd = qkvd + (long)B*GD*HID;  float* vd = qkvd + 2L*B*GD*HID;
    float* pe  = (float*)sym(d_pe);
    float* de  = (float*)sym(d_de);
    int*   mp  = (int*)  sym(d_mp);
    int*   md  = (int*)  sym(d_md);
    float* x   = (float*)sym(d_x);
    float* x1  = (float*)sym(d_x1);
    float* x2  = (float*)sym(d_x2);
    float* x3  = (float*)sym(d_x3);
    float* out = (float*)d_out;

    // 0. classify mask dtype layout
    detect_mask_kernel<<<1, 1>>>((const unsigned char*)prot_mask);

    // 1. grouping (8x FLOP cut; output pre-split bf16 hi/lo) + masks
    {
        long tp = (long)B*GP*(DP/4);
        group_embed_split_kernel<<<(int)((tp + 255)/256), 256>>>((const float4*)prot_embed, pgEh, pgEl, LP, DP/4);
        long td = (long)B*GD*(DD/4);
        group_embed_split_kernel<<<(int)((td + 255)/256), 256>>>((const float4*)drug_embed, dgEh, dgEl, LD, DD/4);
        group_mask_kernel<<<(B*GP + 255)/256, 256>>>(prot_mask, mp, LP);
        group_mask_kernel<<<(B*GD + 255)/256, 256>>>(drug_mask, md, LD);
    }

    // 2. weight transposes + bf16 splits
    {
        const long nHK = (long)HID*HID;
        transpose_split_kernel<<<(int)(((long)HID*DP + 255)/256), 256>>>(w_preg, wpt_h, wpt_l, DP);
        transpose_split_kernel<<<(int)(((long)HID*DD + 255)/256), 256>>>(w_dreg, wdt_h, wdt_l, DD);
        transpose_split_kernel<<<(int)((nHK + 255)/256), 256>>>(wqp, wqpt + 0*nHK, wqpt + 3*nHK, HID);
        transpose_split_kernel<<<(int)((nHK + 255)/256), 256>>>(wkp, wqpt + 1*nHK, wqpt + 4*nHK, HID);
        transpose_split_kernel<<<(int)((nHK + 255)/256), 256>>>(wvp, wqpt + 2*nHK, wqpt + 5*nHK, HID);
        transpose_split_kernel<<<(int)((nHK + 255)/256), 256>>>(wqd, wqdt + 0*nHK, wqdt + 3*nHK, HID);
        transpose_split_kernel<<<(int)((nHK + 255)/256), 256>>>(wkd, wqdt + 1*nHK, wqdt + 4*nHK, HID);
        transpose_split_kernel<<<(int)((nHK + 255)/256), 256>>>(wvd, wqdt + 2*nHK, wqdt + 5*nHK, HID);
    }

    // 3. projection GEMMs (wmma, compensated bf16) -> fp32 scratch (qp/qd), then bias+split
    gemm_wmma_kernel<<<dim3(4, (B*GP)/128, 1), 256>>>(
        pgEh, pgEl, wpt_h, wpt_h, wpt_h, wpt_l, wpt_l, wpt_l,
        qp, qp, qp, DP);
    bias_split_kernel<<<(int)(((long)B*GP*HID + 255)/256), 256>>>(qp, b_preg, pgh, pgl, (long)B*GP*HID);
    gemm_wmma_kernel<<<dim3(4, (B*GD)/128, 1), 256>>>(
        dgEh, dgEl, wdt_h, wdt_h, wdt_h, wdt_l, wdt_l, wdt_l,
        qd, qd, qd, DD);
    bias_split_kernel<<<(int)(((long)B*GD*HID + 255)/256), 256>>>(qd, b_dreg, dgh, dgl, (long)B*GD*HID);

    // 4. q/k/v GEMMs (batched over blockIdx.z) -> fp32 (overwrites scratch after split)
    {
        const long nHK = (long)HID*HID;
        gemm_wmma_kernel<<<dim3(4, (B*GP)/128, 3), 256>>>(
            pgh, pgl, wqpt + 0*nHK, wqpt + 1*nHK, wqpt + 2*nHK,
            wqpt + 3*nHK, wqpt + 4*nHK, wqpt + 5*nHK,
            qp, kp, vp, HID);
        gemm_wmma_kernel<<<dim3(4, (B*GD)/128, 3), 256>>>(
            dgh, dgl, wqdt + 0*nHK, wqdt + 1*nHK, wqdt + 2*nHK,
            wqdt + 3*nHK, wqdt + 4*nHK, wqdt + 5*nHK,
            qd, kd, vd, HID);
    }

    // 5. cross attention: pe = 0.5*(attn(qp,kp,vp)+attn(qp,kd,vd)); de symmetric
    attn_kernel<<<dim3(GP/32, NH, B), 256>>>(qp, kp, vp, mp, mp, pe, GP, GP, 1);
    attn_kernel<<<dim3(GP/32, NH, B), 256>>>(qp, kd, vd, mp, md, pe, GP, GD, 0);
    attn_kernel<<<dim3(GD/32, NH, B), 256>>>(qd, kp, vp, md, mp, de, GD, GP, 1);
    attn_kernel<<<dim3(GD/32, NH, B), 256>>>(qd, kd, vd, md, md, de, GD, GD, 0);

    // 6. masked-mean pooling + concat -> x [32, 1024]
    pool_kernel<<<B, 512>>>(pe, de, mp, md, x);

    // 7. MLP decoder with train-mode BatchNorm
    mlp_layer_kernel<<<1024, 32>>>(x,  w1, b1, g1, be1, x1, 1024, 1024);
    mlp_layer_kernel<<<512,  32>>>(x1, w2, b2, g2, be2, x2, 1024, 512);
    mlp_layer_kernel<<<256,  32>>>(x2, w3, b3, g3, be3, x3, 512,  256);

    // 8. output head
    final_kernel<<<B, 256>>>(x3, wo, bo, out);

    (void)in_sizes; (void)n_in; (void)out_size;
}

// round 12
// speedup vs baseline: 2.5541x; 1.5445x over previous
#include <cuda_runtime.h>
#include <cuda_bf16.h>
#include <mma.h>
#include <math.h>
#include <stdint.h>

using namespace nvcuda;

// ---------------- problem constants ----------------
#define B   32
#define LP  2048
#define LD  512
#define DP  1280
#define DD  768
#define GP  (LP/8)      // 256
#define GD  (LD/8)      // 64
#define HID 512
#define NH  8
#define HD  64
#define INFV 1e6f
#define EPS 1e-5f

// ---------------- device scratch (static; no allocs) ----------------
__device__ __nv_bfloat16 d_pgEh[B*GP*DP], d_pgEl[B*GP*DP];
__device__ __nv_bfloat16 d_dgEh[B*GD*DD], d_dgEl[B*GD*DD];
__device__ __nv_bfloat16 d_pgh [B*GP*HID], d_pgl [B*GP*HID];
__device__ __nv_bfloat16 d_dgh [B*GD*HID], d_dgl [B*GD*HID];
__device__ __nv_bfloat16 d_wpt_h[HID*DP],  d_wpt_l[HID*DP];
__device__ __nv_bfloat16 d_wdt_h[HID*DD],  d_wdt_l[HID*DD];
__device__ __nv_bfloat16 d_wqp_t[2][3][HID*HID];
__device__ __nv_bfloat16 d_wqd_t[2][3][HID*HID];
__device__ float d_qkvp[3][B*GP*HID];
__device__ float d_qkvd[3][B*GD*HID];
__device__ float d_pe [B*GP*HID];
__device__ float d_de [B*GD*HID];
__device__ int   d_mp [B*GP];
__device__ int   d_md [B*GD];
__device__ float d_x  [B*1024];
__device__ float d_x1 [B*1024];
__device__ float d_x2 [B*512];
__device__ float d_x3 [B*256];
__device__ int   d_mask_layout;

// ---------------- small helpers ----------------
__device__ __forceinline__ void bsplit(float x, __nv_bfloat16& h, __nv_bfloat16& l) {
    h = __float2bfloat16(x);
    l = __float2bfloat16(x - __bfloat162float(h));
}
__device__ __forceinline__ void cpa16(uint32_t daddr, const void* g) {
    asm volatile("cp.async.cg.shared.global [%0], [%1], 16;" :: "r"(daddr), "l"(g));
}

// ---------------- mask layout detection (validated) ----------------
__global__ void detect_mask_kernel(const unsigned char* __restrict__ m) {
    int u8 = 0, f32 = 0;
    for (int i = 0; i < 4096; i++) {
        unsigned char v = m[i];
        int r = i & 3;
        if (r != 0 && v != 0) {
            if (v == 1) u8 = 1; else f32 = 1;
        }
    }
    d_mask_layout = u8 ? 1 : (f32 ? 2 : 0);
}
__device__ __forceinline__ int read_mask(const void* m, int idx, int layout) {
    if (layout == 0) return ((const int*)m)[idx] != 0;
    if (layout == 1) return ((const unsigned char*)m)[idx] != 0;
    return ((const float*)m)[idx] != 0.0f;
}

// ---------------- fused mask grouping (prot + drug in one launch) ----------------
__global__ void group_mask_all_kernel(const void* __restrict__ mP, const void* __restrict__ mD,
                                      int* __restrict__ mp, int* __restrict__ md) {
    int idx = blockIdx.x * blockDim.x + threadIdx.x;
    int layout = d_mask_layout;
    if (idx < B*GP) {
        int g = idx % GP, b = idx / GP;
        int any = 0;
        #pragma unroll
        for (int r = 0; r < 8; r++) any |= read_mask(mP, b*LP + g*8 + r, layout);
        mp[idx] = any;
    } else if (idx < B*GP + B*GD) {
        int j = idx - B*GP;
        int g = j % GD, b = j / GD;
        int any = 0;
        #pragma unroll
        for (int r = 0; r < 8; r++) any |= read_mask(mD, b*LD + g*8 + r, layout);
        md[j] = any;
    }
}

// ---------------- grouping: mean over 8 rows -> bf16 hi/lo split ----------------
__global__ void group_embed_split_kernel(const float4* __restrict__ X,
                                         __nv_bfloat16* __restrict__ Yh,
                                         __nv_bfloat16* __restrict__ Yl,
                                         int L, int D4) {
    long idx = (long)blockIdx.x * blockDim.x + threadIdx.x;
    long total = (long)B * (L/8) * D4;
    if (idx >= total) return;
    int d   = (int)(idx % D4);
    long bg = idx / D4;
    int g  = (int)(bg % (L/8));
    int b  = (int)(bg / (L/8));
    const float4* p = X + ((long)b*L + (long)g*8) * D4 + d;
    float sx=0.f, sy=0.f, sz=0.f, sw=0.f;
    #pragma unroll
    for (int r = 0; r < 8; r++) {
        float4 v = p[(long)r*D4];
        sx += v.x; sy += v.y; sz += v.z; sw += v.w;
    }
    __nv_bfloat16 h0,l0,h1,l1,h2,l2,h3,l3;
    bsplit(sx*0.125f, h0, l0); bsplit(sy*0.125f, h1, l1);
    bsplit(sz*0.125f, h2, l2); bsplit(sw*0.125f, h3, l3);
    __nv_bfloat162* yh = (__nv_bfloat162*)Yh;
    __nv_bfloat162* yl = (__nv_bfloat162*)Yl;
    yh[idx*2+0] = __nv_bfloat162(h0, h1); yh[idx*2+1] = __nv_bfloat162(h2, h3);
    yl[idx*2+0] = __nv_bfloat162(l0, l1); yl[idx*2+1] = __nv_bfloat162(l2, l3);
}

// ---------------- fused weight transposes + bf16 split (8 jobs, one launch) ----------------
struct TSJob  { const float* W; __nv_bfloat16 *Th, *Tl; int K; };
struct TSJobs { TSJob j[8]; };
__global__ void transpose_all_kernel(TSJobs jobs) {
    TSJob jb = jobs.j[blockIdx.y];
    long idx = (long)blockIdx.x * blockDim.x + threadIdx.x;
    if (idx >= (long)HID * jb.K) return;
    int k = (int)(idx % jb.K), n = (int)(idx / jb.K);
    float v = jb.W[(long)k * HID + n];
    __nv_bfloat16 h, l; bsplit(v, h, l);
    jb.Th[idx] = h; jb.Tl[idx] = l;
}

// ---------------- bias add + bf16 split (proj epilogue) ----------------
__global__ void bias_split_kernel(const float* __restrict__ C, const float* __restrict__ bias,
                                  __nv_bfloat16* __restrict__ Yh, __nv_bfloat16* __restrict__ Yl,
                                  long total) {
    long idx = (long)blockIdx.x * blockDim.x + threadIdx.x;
    if (idx >= total) return;
    float v = C[idx] + bias[idx & (HID-1)];
    __nv_bfloat16 h, l; bsplit(v, h, l);
    Yh[idx] = h; Yl[idx] = l;
}

// ---------------- wmma GEMM, cp.async double-buffered ----------------
// C[M,512] = A[M,K] @ T[512,K]^T ; compensated bf16: Ah*Bh + Al*Bh + Ah*Bl.
// 128x128 CTA tile; 8 warps (warp tile 32x64); K in 32-chunks, 2-deep pipeline.
#define GT_PAD 40
#define GT_ARR (128*GT_PAD)                 // elements per operand per buffer
#define GT_BUF (4*GT_ARR)                   // Ah|Al|Bh|Bl
#define GT_SMEM (2*GT_BUF*2)                // bytes (double buffer, bf16)
__global__ __launch_bounds__(256) void gemm_wmma_kernel(
    const __nv_bfloat16* __restrict__ Ahi, const __nv_bfloat16* __restrict__ Alo,
    const __nv_bfloat16* __restrict__ Wh0, const __nv_bfloat16* __restrict__ Wh1,
    const __nv_bfloat16* __restrict__ Wh2,
    const __nv_bfloat16* __restrict__ Wl0, const __nv_bfloat16* __restrict__ Wl1,
    const __nv_bfloat16* __restrict__ Wl2,
    float* __restrict__ C0, float* __restrict__ C1, float* __restrict__ C2,
    int K)
{
    extern __shared__ __nv_bfloat16 smem[];
    const __nv_bfloat16* Wh = (blockIdx.z == 0) ? Wh0 : (blockIdx.z == 1) ? Wh1 : Wh2;
    const __nv_bfloat16* Wl = (blockIdx.z == 0) ? Wl0 : (blockIdx.z == 1) ? Wl1 : Wl2;
    float* C                = (blockIdx.z == 0) ? C0  : (blockIdx.z == 1) ? C1  : C2;

    const int tid  = threadIdx.x;
    const int warp = tid >> 5;
    const int wm   = warp & 3;              // 4 M-warps x 32 rows
    const int wn   = warp >> 2;             // 2 N-warps x 64 cols
    const int rowBase = blockIdx.y * 128, nBase = blockIdx.x * 128;
    const int nCh = K >> 5;

    wmma::fragment<wmma::accumulator, 16, 16, 16, float> acc[2][4];
    #pragma unroll
    for (int mi = 0; mi < 2; mi++)
        #pragma unroll
        for (int ni = 0; ni < 4; ni++) wmma::fill_fragment(acc[mi][ni], 0.f);

    // stage chunk ch into buffer buf via cp.async (each thread: 8 x 16B)
    auto stage = [&](int ch, int buf) {
        const int k0 = ch << 5;
        __nv_bfloat16* s = smem + buf * GT_BUF;
        for (int u = tid; u < 512; u += 256) {
            int r = u >> 2, c8 = (u & 3) << 3;
            long ga = (long)(rowBase + r) * K + k0 + c8;
            long gb = (long)(nBase   + r) * K + k0 + c8;
            uint32_t d0 = (uint32_t)__cvta_generic_to_shared(s + r*GT_PAD + c8);
            cpa16(d0,               Ahi + ga);
            cpa16(d0 + 2*GT_ARR,    Alo + ga);
            cpa16(d0 + 4*GT_ARR,    Wh  + gb);
            cpa16(d0 + 6*GT_ARR,    Wl  + gb);
        }
    };

    stage(0, 0);
    asm volatile("cp.async.commit_group;" ::: "memory");

    for (int ch = 0; ch < nCh; ch++) {
        const int buf = ch & 1;
        if (ch + 1 < nCh) {
            stage(ch + 1, 1 - buf);
            asm volatile("cp.async.commit_group;" ::: "memory");
            asm volatile("cp.async.wait_group 1;" ::: "memory");
        } else {
            asm volatile("cp.async.wait_group 0;" ::: "memory");
        }
        __syncthreads();

        const __nv_bfloat16* sAh = smem + buf*GT_BUF;
        const __nv_bfloat16* sAl = sAh + GT_ARR;
        const __nv_bfloat16* sBh = sAh + 2*GT_ARR;
        const __nv_bfloat16* sBl = sAh + 3*GT_ARR;

        #pragma unroll
        for (int ks = 0; ks < 2; ks++) {
            wmma::fragment<wmma::matrix_a, 16, 16, 16, __nv_bfloat16, wmma::row_major> a_h[2], a_l[2];
            #pragma unroll
            for (int mi = 0; mi < 2; mi++) {
                int r = (wm*32 + mi*16) * GT_PAD + ks*16;
                wmma::load_matrix_sync(a_h[mi], sAh + r, GT_PAD);
                wmma::load_matrix_sync(a_l[mi], sAl + r, GT_PAD);
            }
            #pragma unroll
            for (int ni = 0; ni < 4; ni++) {
                wmma::fragment<wmma::matrix_b, 16, 16, 16, __nv_bfloat16, wmma::col_major> b_h, b_l;
                int r = (wn*64 + ni*16) * GT_PAD + ks*16;
                wmma::load_matrix_sync(b_h, sBh + r, GT_PAD);
                wmma::load_matrix_sync(b_l, sBl + r, GT_PAD);
                #pragma unroll
                for (int mi = 0; mi < 2; mi++) {
                    wmma::mma_sync(acc[mi][ni], a_h[mi], b_h, acc[mi][ni]);
                    wmma::mma_sync(acc[mi][ni], a_l[mi], b_h, acc[mi][ni]);
                    wmma::mma_sync(acc[mi][ni], a_h[mi], b_l, acc[mi][ni]);
                }
            }
        }
        __syncthreads();
    }

    #pragma unroll
    for (int mi = 0; mi < 2; mi++)
        #pragma unroll
        for (int ni = 0; ni < 4; ni++) {
            long off = (long)(rowBase + wm*32 + mi*16) * HID + nBase + wn*64 + ni*16;
            wmma::store_matrix_sync(C + off, acc[mi][ni], HID, wmma::mem_row_major);
        }
}

// ---------------- merged masked attention: both K/V sources, one output write ----------------
// out[b,i,h,:] = 0.5*(softmax0 @ V0 + softmax1 @ V1), row-masked. 4 q rows/warp.
__global__ __launch_bounds__(256) void attn2_kernel(
    const float* __restrict__ Q,
    const float* __restrict__ K0, const float* __restrict__ V0,
    const int* __restrict__ mc0, int Gk0,
    const float* __restrict__ K1, const float* __restrict__ V1,
    const int* __restrict__ mc1, int Gk1,
    const int* __restrict__ mrow, float* __restrict__ out, int Gq)
{
    const int b = blockIdx.z, h = blockIdx.y;
    const int warp = threadIdx.x >> 5, lane = threadIdx.x & 31;
    const int qtile = blockIdx.x * 32;
    const int r0 = warp * 4;

    __shared__ float Qs[32][68];
    __shared__ float Ks[32][68];
    __shared__ float Vs[32][68];
    __shared__ int   mcs[32];

    for (int t = threadIdx.x; t < 512; t += 256) {
        int r = t >> 4, c4 = (t & 15) * 4;
        *(float4*)&Qs[r][c4] = *(const float4*)(Q + ((long)(b*Gq + qtile + r) * HID) + h*HD + c4);
    }
    int mr[4];
    #pragma unroll
    for (int r = 0; r < 4; r++) mr[r] = mrow[b*Gq + qtile + r0 + r];

    float res0[4] = {0.f,0.f,0.f,0.f}, res1[4] = {0.f,0.f,0.f,0.f};

    #pragma unroll
    for (int s = 0; s < 2; s++) {
        const float* Kc = s ? K1 : K0;
        const float* Vc = s ? V1 : V0;
        const int*   mc = s ? mc1 : mc0;
        const int    Gk = s ? Gk1 : Gk0;

        float mmax[4], lsum[4], a0[4], a1[4];
        #pragma unroll
        for (int r = 0; r < 4; r++) { mmax[r] = -1e30f; lsum[r] = 0.f; a0[r] = 0.f; a1[r] = 0.f; }

        for (int j0 = 0; j0 < Gk; j0 += 32) {
            __syncthreads();
            for (int t = threadIdx.x; t < 512; t += 256) {
                int r = t >> 4, c4 = (t & 15) * 4;
                long base = ((long)(b*Gk + j0 + r) * HID) + h*HD + c4;
                *(float4*)&Ks[r][c4] = *(const float4*)(Kc + base);
                *(float4*)&Vs[r][c4] = *(const float4*)(Vc + base);
            }
            if (threadIdx.x < 32) mcs[threadIdx.x] = mc[b*Gk + j0 + threadIdx.x];
            __syncthreads();

            float lg[4] = {0.f, 0.f, 0.f, 0.f};
            #pragma unroll
            for (int d4 = 0; d4 < HD; d4 += 4) {
                float4 kv = *(const float4*)&Ks[lane][d4];
                #pragma unroll
                for (int r = 0; r < 4; r++) {
                    float4 qv = *(const float4*)&Qs[r0 + r][d4];
                    lg[r] += qv.x*kv.x + qv.y*kv.y + qv.z*kv.z + qv.w*kv.w;
                }
            }
            const int mcl = mcs[lane];
            float pr[4];
            #pragma unroll
            for (int r = 0; r < 4; r++) {
                float logit = (mr[r] && mcl) ? lg[r] : lg[r] - INFV;   // exact reference semantics
                float cm = logit;
                #pragma unroll
                for (int o = 16; o; o >>= 1) cm = fmaxf(cm, __shfl_xor_sync(0xffffffffu, cm, o));
                float mnew  = fmaxf(mmax[r], cm);
                float sc    = __expf(mmax[r] - mnew);
                pr[r]       = __expf(logit - mnew);
                float ps = pr[r];
                #pragma unroll
                for (int o = 16; o; o >>= 1) ps += __shfl_xor_sync(0xffffffffu, ps, o);
                lsum[r] = lsum[r]*sc + ps;
                a0[r] *= sc; a1[r] *= sc;
                mmax[r] = mnew;
            }
            #pragma unroll
            for (int jj = 0; jj < 32; jj += 2) {
                float2 v0 = *(const float2*)&Vs[jj+0][lane*2];
                float2 v1 = *(const float2*)&Vs[jj+1][lane*2];
                #pragma unroll
                for (int r = 0; r < 4; r++) {
                    float p0 = __shfl_sync(0xffffffffu, pr[r], jj+0);
                    float p1 = __shfl_sync(0xffffffffu, pr[r], jj+1);
                    a0[r] += p0*v0.x + p1*v1.x;
                    a1[r] += p0*v0.y + p1*v1.y;
                }
            }
        }
        #pragma unroll
        for (int r = 0; r < 4; r++) {
            float inv = 1.f / lsum[r];
            res0[r] += a0[r] * inv;
            res1[r] += a1[r] * inv;
        }
    }

    #pragma unroll
    for (int r = 0; r < 4; r++) {
        float* op = out + ((long)(b*Gq + qtile + r0 + r) * HID) + h*HD + lane*2;
        op[0] = mr[r] ? res0[r] * 0.5f : 0.f;
        op[1] = mr[r] ? res1[r] * 0.5f : 0.f;
    }
}

// ---------------- masked mean pooling + concat ----------------
__global__ void pool_kernel(const float* __restrict__ pe, const float* __restrict__ de,
                            const int* __restrict__ mp, const int* __restrict__ md,
                            float* __restrict__ x)
{
    int b = blockIdx.x, d = threadIdx.x;
    float cp = 0.f, sp = 0.f;
    for (int g = 0; g < GP; g++) {
        float m = (float)mp[b*GP + g];
        cp += m;
        sp += m * pe[((long)b*GP + g) * HID + d];
    }
    x[b*1024 + d] = sp / cp;
    float cd = 0.f, sd = 0.f;
    for (int g = 0; g < GD; g++) {
        float m = (float)md[b*GD + g];
        cd += m;
        sd += m * de[((long)b*GD + g) * HID + d];
    }
    x[b*1024 + 512 + d] = sd / cd;
}

// ---------------- MLP layer: relu(X@W+b) then train-mode BN over batch ----------------
__global__ void mlp_layer_kernel(const float* __restrict__ X, const float* __restrict__ Wm,
                                 const float* __restrict__ bias, const float* __restrict__ gamma,
                                 const float* __restrict__ beta, float* __restrict__ Y,
                                 int Kdim, int N)
{
    int n = blockIdx.x, b = threadIdx.x;
    float s = bias[n];
    for (int k = 0; k < Kdim; k++) s += X[b*Kdim + k] * Wm[(long)k*N + n];
    s = fmaxf(s, 0.f);
    float mu = s;
    #pragma unroll
    for (int o = 16; o; o >>= 1) mu += __shfl_xor_sync(0xffffffffu, mu, o);
    mu *= (1.f/32.f);
    float diff = s - mu;
    float var = diff * diff;
    #pragma unroll
    for (int o = 16; o; o >>= 1) var += __shfl_xor_sync(0xffffffffu, var, o);
    var *= (1.f/32.f);
    Y[b*N + n] = gamma[n] * diff * rsqrtf(var + EPS) + beta[n];
}

// ---------------- final: sigmoid(x3 @ wo + bo) ----------------
__global__ void final_kernel(const float* __restrict__ X3, const float* __restrict__ wo,
                             const float* __restrict__ bo, float* __restrict__ out)
{
    int b = blockIdx.x, t = threadIdx.x;
    __shared__ float red[256];
    red[t] = X3[b*256 + t] * wo[t];
    __syncthreads();
    for (int st = 128; st; st >>= 1) {
        if (t < st) red[t] += red[t + st];
        __syncthreads();
    }
    if (t == 0) out[b] = 1.f / (1.f + __expf(-(red[0] + bo[0])));
}

// ---------------- launch ----------------
static void* sym(const void* s) { void* p = nullptr; cudaGetSymbolAddress(&p, s); return p; }

extern "C" void kernel_launch(void* const* d_in, const int* in_sizes, int n_in,
                              void* d_out, int out_size)
{
    const float* prot_embed = (const float*)d_in[0];
    const float* drug_embed = (const float*)d_in[1];
    const void*  prot_mask  = d_in[2];
    const void*  drug_mask  = d_in[3];
    const float* w_preg = (const float*)d_in[4];
    const float* b_preg = (const float*)d_in[5];
    const float* w_dreg = (const float*)d_in[6];
    const float* b_dreg = (const float*)d_in[7];
    const float* wqp = (const float*)d_in[8];
    const float* wkp = (const float*)d_in[9];
    const float* wvp = (const float*)d_in[10];
    const float* wqd = (const float*)d_in[11];
    const float* wkd = (const float*)d_in[12];
    const float* wvd = (const float*)d_in[13];
    const float* w1  = (const float*)d_in[14];
    const float* b1  = (const float*)d_in[15];
    const float* g1  = (const float*)d_in[16];
    const float* be1 = (const float*)d_in[17];
    const float* w2  = (const float*)d_in[18];
    const float* b2  = (const float*)d_in[19];
    const float* g2  = (const float*)d_in[20];
    const float* be2 = (const float*)d_in[21];
    const float* w3  = (const float*)d_in[22];
    const float* b3  = (const float*)d_in[23];
    const float* g3  = (const float*)d_in[24];
    const float* be3 = (const float*)d_in[25];
    const float* wo  = (const float*)d_in[26];
    const float* bo  = (const float*)d_in[27];

    __nv_bfloat16* pgEh = (__nv_bfloat16*)sym(d_pgEh);
    __nv_bfloat16* pgEl = (__nv_bfloat16*)sym(d_pgEl);
    __nv_bfloat16* dgEh = (__nv_bfloat16*)sym(d_dgEh);
    __nv_bfloat16* dgEl = (__nv_bfloat16*)sym(d_dgEl);
    __nv_bfloat16* pgh  = (__nv_bfloat16*)sym(d_pgh);
    __nv_bfloat16* pgl  = (__nv_bfloat16*)sym(d_pgl);
    __nv_bfloat16* dgh  = (__nv_bfloat16*)sym(d_dgh);
    __nv_bfloat16* dgl  = (__nv_bfloat16*)sym(d_dgl);
    __nv_bfloat16* wpt_h = (__nv_bfloat16*)sym(d_wpt_h);
    __nv_bfloat16* wpt_l = (__nv_bfloat16*)sym(d_wpt_l);
    __nv_bfloat16* wdt_h = (__nv_bfloat16*)sym(d_wdt_h);
    __nv_bfloat16* wdt_l = (__nv_bfloat16*)sym(d_wdt_l);
    __nv_bfloat16* wqpt  = (__nv_bfloat16*)sym(d_wqp_t);
    __nv_bfloat16* wqdt  = (__nv_bfloat16*)sym(d_wqd_t);
    float* qkvp = (float*)sym(d_qkvp);
    float* qkvd = (float*)sym(d_qkvd);
    float* qp = qkvp;  float* kp = qkvp + (long)B*GP*HID;  float* vp = qkvp + 2L*B*GP*HID;
    float* qd = qkvd;  float* kd = qkvd + (long)B*GD*HID;  float* vd = qkvd + 2L*B*GD*HID;
    float* pe  = (float*)sym(d_pe);
    float* de  = (float*)sym(d_de);
    int*   mp  = (int*)  sym(d_mp);
    int*   md  = (int*)  sym(d_md);
    float* x   = (float*)sym(d_x);
    float* x1  = (float*)sym(d_x1);
    float* x2  = (float*)sym(d_x2);
    float* x3  = (float*)sym(d_x3);
    float* out = (float*)d_out;

    cudaFuncSetAttribute(gemm_wmma_kernel, cudaFuncAttributeMaxDynamicSharedMemorySize, GT_SMEM);

    const long nHK = (long)HID*HID;

    // launch 0: mask dtype classification
    detect_mask_kernel<<<1, 1>>>((const unsigned char*)prot_mask);

    // launch 1: all 8 weight transposes + splits, fused
    {
        TSJobs jobs;
        jobs.j[0] = { w_preg, wpt_h, wpt_l, DP };
        jobs.j[1] = { w_dreg, wdt_h, wdt_l, DD };
        jobs.j[2] = { wqp, wqpt + 0*nHK, wqpt + 3*nHK, HID };
        jobs.j[3] = { wkp, wqpt + 1*nHK, wqpt + 4*nHK, HID };
        jobs.j[4] = { wvp, wqpt + 2*nHK, wqpt + 5*nHK, HID };
        jobs.j[5] = { wqd, wqdt + 0*nHK, wqdt + 3*nHK, HID };
        jobs.j[6] = { wkd, wqdt + 1*nHK, wqdt + 4*nHK, HID };
        jobs.j[7] = { wvd, wqdt + 2*nHK, wqdt + 5*nHK, HID };
        int gx = (int)(((long)HID*DP + 255)/256);
        transpose_all_kernel<<<dim3(gx, 8), 256>>>(jobs);
    }

    // launch 2: fused mask grouping
    group_mask_all_kernel<<<(B*GP + B*GD + 255)/256, 256>>>(prot_mask, drug_mask, mp, md);

    // launches 3,4: embedding grouping + split
    {
        long tp = (long)B*GP*(DP/4);
        group_embed_split_kernel<<<(int)((tp + 255)/256), 256>>>((const float4*)prot_embed, pgEh, pgEl, LP, DP/4);
        long td = (long)B*GD*(DD/4);
        group_embed_split_kernel<<<(int)((td + 255)/256), 256>>>((const float4*)drug_embed, dgEh, dgEl, LD, DD/4);
    }

    // launch 5 (ncu target): projection GEMM prot
    gemm_wmma_kernel<<<dim3(4, (B*GP)/128, 1), 256, GT_SMEM>>>(
        pgEh, pgEl, wpt_h, wpt_h, wpt_h, wpt_l, wpt_l, wpt_l,
        qp, qp, qp, DP);
    bias_split_kernel<<<(int)(((long)B*GP*HID + 255)/256), 256>>>(qp, b_preg, pgh, pgl, (long)B*GP*HID);
    gemm_wmma_kernel<<<dim3(4, (B*GD)/128, 1), 256, GT_SMEM>>>(
        dgEh, dgEl, wdt_h, wdt_h, wdt_h, wdt_l, wdt_l, wdt_l,
        qd, qd, qd, DD);
    bias_split_kernel<<<(int)(((long)B*GD*HID + 255)/256), 256>>>(qd, b_dreg, dgh, dgl, (long)B*GD*HID);

    // q/k/v GEMMs (batched over blockIdx.z)
    gemm_wmma_kernel<<<dim3(4, (B*GP)/128, 3), 256, GT_SMEM>>>(
        pgh, pgl, wqpt + 0*nHK, wqpt + 1*nHK, wqpt + 2*nHK,
        wqpt + 3*nHK, wqpt + 4*nHK, wqpt + 5*nHK,
        qp, kp, vp, HID);
    gemm_wmma_kernel<<<dim3(4, (B*GD)/128, 3), 256, GT_SMEM>>>(
        dgh, dgl, wqdt + 0*nHK, wqdt + 1*nHK, wqdt + 2*nHK,
        wqdt + 3*nHK, wqdt + 4*nHK, wqdt + 5*nHK,
        qd, kd, vd, HID);

    // merged cross attention (one launch per query side, single output write)
    attn2_kernel<<<dim3(GP/32, NH, B), 256>>>(qp, kp, vp, mp, GP, kd, vd, md, GD, mp, pe, GP);
    attn2_kernel<<<dim3(GD/32, NH, B), 256>>>(qd, kp, vp, mp, GP, kd, vd, md, GD, md, de, GD);

    // masked-mean pooling + concat -> x [32, 1024]
    pool_kernel<<<B, 512>>>(pe, de, mp, md, x);

    // MLP decoder with train-mode BatchNorm
    mlp_layer_kernel<<<1024, 32>>>(x,  w1, b1, g1, be1, x1, 1024, 1024);
    mlp_layer_kernel<<<512,  32>>>(x1, w2, b2, g2, be2, x2, 1024, 512);
    mlp_layer_kernel<<<256,  32>>>(x2, w3, b3, g3, be3, x3, 512,  256);

    // output head
    final_kernel<<<B, 256>>>(x3, wo, bo, out);

    (void)in_sizes; (void)n_in; (void)out_size;
}

// round 14
// speedup vs baseline: 2.7721x; 1.0854x over previous
#include <cuda_runtime.h>
#include <cuda_bf16.h>
#include <mma.h>
#include <math.h>
#include <stdint.h>

using namespace nvcuda;

// ---------------- problem constants ----------------
#define B   32
#define LP  2048
#define LD  512
#define DP  1280
#define DD  768
#define GP  (LP/8)      // 256
#define GD  (LD/8)      // 64
#define HID 512
#define NH  8
#define HD  64
#define INFV 1e6f
#define EPS 1e-5f

// ---------------- device scratch (static; no allocs) ----------------
__device__ __nv_bfloat16 d_pgEh[B*GP*DP], d_pgEl[B*GP*DP];
__device__ __nv_bfloat16 d_dgEh[B*GD*DD], d_dgEl[B*GD*DD];
__device__ __nv_bfloat16 d_pgh [B*GP*HID], d_pgl [B*GP*HID];
__device__ __nv_bfloat16 d_dgh [B*GD*HID], d_dgl [B*GD*HID];
__device__ __nv_bfloat16 d_wpt_h[HID*DP],  d_wpt_l[HID*DP];
__device__ __nv_bfloat16 d_wdt_h[HID*DD],  d_wdt_l[HID*DD];
__device__ __nv_bfloat16 d_wqp_t[2][3][HID*HID];
__device__ __nv_bfloat16 d_wqd_t[2][3][HID*HID];
__device__ float d_qkvp[3][B*GP*HID];
__device__ float d_qkvd[3][B*GD*HID];
__device__ float d_pe [B*GP*HID];
__device__ float d_de [B*GD*HID];
__device__ int   d_mp [B*GP];
__device__ int   d_md [B*GD];
__device__ float d_x  [B*1024];
__device__ float d_x1 [B*1024];
__device__ float d_x2 [B*512];
__device__ float d_x3 [B*256];
__device__ int   d_mask_layout;

// ---------------- small helpers ----------------
__device__ __forceinline__ void bsplit(float x, __nv_bfloat16& h, __nv_bfloat16& l) {
    h = __float2bfloat16(x);
    l = __float2bfloat16(x - __bfloat162float(h));
}
__device__ __forceinline__ void cpa16(uint32_t daddr, const void* g) {
    asm volatile("cp.async.cg.shared.global [%0], [%1], 16;" :: "r"(daddr), "l"(g));
}

// ---------------- mask layout detection (parallel; 256 threads x 16B) ----------------
__global__ void detect_mask_kernel(const unsigned char* __restrict__ m) {
    __shared__ int fu8, ff32;
    if (threadIdx.x == 0) { fu8 = 0; ff32 = 0; }
    __syncthreads();
    int u8 = 0, f32 = 0;
    const int base = threadIdx.x * 16;
    #pragma unroll
    for (int i = base; i < base + 16; i++) {
        unsigned char v = m[i];
        int r = i & 3;
        if (r != 0 && v != 0) { if (v == 1) u8 = 1; else f32 = 1; }
    }
    if (u8)  atomicOr(&fu8, 1);
    if (f32) atomicOr(&ff32, 1);
    __syncthreads();
    if (threadIdx.x == 0) d_mask_layout = fu8 ? 1 : (ff32 ? 2 : 0);
}
__device__ __forceinline__ int read_mask(const void* m, int idx, int layout) {
    if (layout == 0) return ((const int*)m)[idx] != 0;
    if (layout == 1) return ((const unsigned char*)m)[idx] != 0;
    return ((const float*)m)[idx] != 0.0f;
}

// ---------------- fused mask grouping (prot + drug in one launch) ----------------
__global__ void group_mask_all_kernel(const void* __restrict__ mP, const void* __restrict__ mD,
                                      int* __restrict__ mp, int* __restrict__ md) {
    int idx = blockIdx.x * blockDim.x + threadIdx.x;
    int layout = d_mask_layout;
    if (idx < B*GP) {
        int g = idx % GP, b = idx / GP;
        int any = 0;
        #pragma unroll
        for (int r = 0; r < 8; r++) any |= read_mask(mP, b*LP + g*8 + r, layout);
        mp[idx] = any;
    } else if (idx < B*GP + B*GD) {
        int j = idx - B*GP;
        int g = j % GD, b = j / GD;
        int any = 0;
        #pragma unroll
        for (int r = 0; r < 8; r++) any |= read_mask(mD, b*LD + g*8 + r, layout);
        md[j] = any;
    }
}

// ---------------- grouping: mean over 8 rows -> bf16 hi/lo split (HBM-roof, keep) ----------------
__global__ void group_embed_split_kernel(const float4* __restrict__ X,
                                         __nv_bfloat16* __restrict__ Yh,
                                         __nv_bfloat16* __restrict__ Yl,
                                         int L, int D4) {
    long idx = (long)blockIdx.x * blockDim.x + threadIdx.x;
    long total = (long)B * (L/8) * D4;
    if (idx >= total) return;
    int d   = (int)(idx % D4);
    long bg = idx / D4;
    int g  = (int)(bg % (L/8));
    int b  = (int)(bg / (L/8));
    const float4* p = X + ((long)b*L + (long)g*8) * D4 + d;
    float sx=0.f, sy=0.f, sz=0.f, sw=0.f;
    #pragma unroll
    for (int r = 0; r < 8; r++) {
        float4 v = p[(long)r*D4];
        sx += v.x; sy += v.y; sz += v.z; sw += v.w;
    }
    __nv_bfloat16 h0,l0,h1,l1,h2,l2,h3,l3;
    bsplit(sx*0.125f, h0, l0); bsplit(sy*0.125f, h1, l1);
    bsplit(sz*0.125f, h2, l2); bsplit(sw*0.125f, h3, l3);
    __nv_bfloat162* yh = (__nv_bfloat162*)Yh;
    __nv_bfloat162* yl = (__nv_bfloat162*)Yl;
    yh[idx*2+0] = __nv_bfloat162(h0, h1); yh[idx*2+1] = __nv_bfloat162(h2, h3);
    yl[idx*2+0] = __nv_bfloat162(l0, l1); yl[idx*2+1] = __nv_bfloat162(l2, l3);
}

// ---------------- smem-tiled weight transpose + bf16 split (8 jobs, one launch) ----------------
struct TSJob  { const float* W; __nv_bfloat16 *Th, *Tl; int K; };
struct TSJobs { TSJob j[8]; };
__global__ void transpose_all_kernel(TSJobs jobs) {
    TSJob jb = jobs.j[blockIdx.z];
    int k0 = blockIdx.x * 32, n0 = blockIdx.y * 32;
    if (k0 >= jb.K) return;
    __shared__ __nv_bfloat16 th[32][33], tl[32][33];
    int tx = threadIdx.x, ty = threadIdx.y;   // (32, 8)
    #pragma unroll
    for (int i = 0; i < 4; i++) {
        int kk = ty + i*8;
        float v = jb.W[(long)(k0 + kk) * HID + n0 + tx];   // coalesced (n fast)
        bsplit(v, th[kk][tx], tl[kk][tx]);
    }
    __syncthreads();
    #pragma unroll
    for (int i = 0; i < 4; i++) {
        int nn = ty + i*8;
        long o = (long)(n0 + nn) * jb.K + k0 + tx;          // coalesced (k fast)
        jb.Th[o] = th[tx][nn];
        jb.Tl[o] = tl[tx][nn];
    }
}

// ---------------- wmma GEMM, cp.async double-buffered, job-batched ----------------
// C[M,512] = A[M,K] @ T[512,K]^T ; compensated bf16: Ah*Bh + Al*Bh + Ah*Bl.
// 128x128 CTA tile; 8 warps (warp tile 32x64); K in 32-chunks, 2-deep pipeline.
// Job table batches prot+drug in one launch; blockIdx.z picks q/k/v weight set.
// Epilogue: fp32 store (C) OR fused bias + bf16 hi/lo split store (Yh/Yl).
#define GT_PAD 40
#define GT_ARR (128*GT_PAD)
#define GT_BUF (4*GT_ARR)
#define GT_SMEM (2*GT_BUF*2)
struct GJob {
    const __nv_bfloat16 *Ah, *Al;
    const __nv_bfloat16 *Wh0, *Wh1, *Wh2, *Wl0, *Wl1, *Wl2;
    float *C0, *C1, *C2;
    const float* bias;
    __nv_bfloat16 *Yh, *Yl;
    int K, tiles;
};
struct GJobs { GJob j[2]; };
__global__ __launch_bounds__(256) void gemm_wmma_kernel(GJobs jobs) {
    extern __shared__ __nv_bfloat16 smem[];
    int yt = blockIdx.y;
    GJob jb = jobs.j[0];
    if (yt >= jb.tiles) { yt -= jb.tiles; jb = jobs.j[1]; }

    const __nv_bfloat16* Wh = (blockIdx.z == 0) ? jb.Wh0 : (blockIdx.z == 1) ? jb.Wh1 : jb.Wh2;
    const __nv_bfloat16* Wl = (blockIdx.z == 0) ? jb.Wl0 : (blockIdx.z == 1) ? jb.Wl1 : jb.Wl2;
    float* C                = (blockIdx.z == 0) ? jb.C0  : (blockIdx.z == 1) ? jb.C1  : jb.C2;
    const __nv_bfloat16* Ahi = jb.Ah;
    const __nv_bfloat16* Alo = jb.Al;
    const int K = jb.K;

    const int tid  = threadIdx.x;
    const int warp = tid >> 5;
    const int lane = tid & 31;
    const int wm   = warp & 3;
    const int wn   = warp >> 2;
    const int rowBase = yt * 128, nBase = blockIdx.x * 128;
    const int nCh = K >> 5;

    wmma::fragment<wmma::accumulator, 16, 16, 16, float> acc[2][4];
    #pragma unroll
    for (int mi = 0; mi < 2; mi++)
        #pragma unroll
        for (int ni = 0; ni < 4; ni++) wmma::fill_fragment(acc[mi][ni], 0.f);

    auto stage = [&](int ch, int buf) {
        const int k0 = ch << 5;
        __nv_bfloat16* s = smem + buf * GT_BUF;
        for (int u = tid; u < 512; u += 256) {
            int r = u >> 2, c8 = (u & 3) << 3;
            long ga = (long)(rowBase + r) * K + k0 + c8;
            long gb = (long)(nBase   + r) * K + k0 + c8;
            uint32_t d0 = (uint32_t)__cvta_generic_to_shared(s + r*GT_PAD + c8);
            cpa16(d0,            Ahi + ga);
            cpa16(d0 + 2*GT_ARR, Alo + ga);
            cpa16(d0 + 4*GT_ARR, Wh  + gb);
            cpa16(d0 + 6*GT_ARR, Wl  + gb);
        }
    };

    stage(0, 0);
    asm volatile("cp.async.commit_group;" ::: "memory");

    for (int ch = 0; ch < nCh; ch++) {
        const int buf = ch & 1;
        if (ch + 1 < nCh) {
            stage(ch + 1, 1 - buf);
            asm volatile("cp.async.commit_group;" ::: "memory");
            asm volatile("cp.async.wait_group 1;" ::: "memory");
        } else {
            asm volatile("cp.async.wait_group 0;" ::: "memory");
        }
        __syncthreads();

        const __nv_bfloat16* sAh = smem + buf*GT_BUF;
        const __nv_bfloat16* sAl = sAh + GT_ARR;
        const __nv_bfloat16* sBh = sAh + 2*GT_ARR;
        const __nv_bfloat16* sBl = sAh + 3*GT_ARR;

        #pragma unroll
        for (int ks = 0; ks < 2; ks++) {
            wmma::fragment<wmma::matrix_a, 16, 16, 16, __nv_bfloat16, wmma::row_major> a_h[2], a_l[2];
            #pragma unroll
            for (int mi = 0; mi < 2; mi++) {
                int r = (wm*32 + mi*16) * GT_PAD + ks*16;
                wmma::load_matrix_sync(a_h[mi], sAh + r, GT_PAD);
                wmma::load_matrix_sync(a_l[mi], sAl + r, GT_PAD);
            }
            #pragma unroll
            for (int ni = 0; ni < 4; ni++) {
                wmma::fragment<wmma::matrix_b, 16, 16, 16, __nv_bfloat16, wmma::col_major> b_h, b_l;
                int r = (wn*64 + ni*16) * GT_PAD + ks*16;
                wmma::load_matrix_sync(b_h, sBh + r, GT_PAD);
                wmma::load_matrix_sync(b_l, sBl + r, GT_PAD);
                #pragma unroll
                for (int mi = 0; mi < 2; mi++) {
                    wmma::mma_sync(acc[mi][ni], a_h[mi], b_h, acc[mi][ni]);
                    wmma::mma_sync(acc[mi][ni], a_l[mi], b_h, acc[mi][ni]);
                    wmma::mma_sync(acc[mi][ni], a_h[mi], b_l, acc[mi][ni]);
                }
            }
        }
        __syncthreads();
    }

    if (jb.Yh == nullptr) {
        // fp32 output (qkv GEMMs)
        #pragma unroll
        for (int mi = 0; mi < 2; mi++)
            #pragma unroll
            for (int ni = 0; ni < 4; ni++) {
                long off = (long)(rowBase + wm*32 + mi*16) * HID + nBase + wn*64 + ni*16;
                wmma::store_matrix_sync(C + off, acc[mi][ni], HID, wmma::mem_row_major);
            }
    } else {
        // fused bias + bf16 hi/lo split (projection GEMM); warp-private smem roundtrip
        float* fs = (float*)smem + warp * 320;   // 16x20 fp32 tile per warp
        #pragma unroll
        for (int mi = 0; mi < 2; mi++)
            #pragma unroll
            for (int ni = 0; ni < 4; ni++) {
                wmma::store_matrix_sync(fs, acc[mi][ni], 20, wmma::mem_row_major);
                __syncwarp();
                int row0 = rowBase + wm*32 + mi*16;
                int col0 = nBase + wn*64 + ni*16;
                #pragma unroll
                for (int e = lane; e < 256; e += 32) {
                    int r = e >> 4, c = e & 15;
                    float v = fs[r*20 + c] + jb.bias[col0 + c];
                    __nv_bfloat16 h, l; bsplit(v, h, l);
                    long o = (long)(row0 + r) * HID + col0 + c;
                    jb.Yh[o] = h; jb.Yl[o] = l;
                }
                __syncwarp();
            }
    }
}

// ---------------- merged masked attention: both K/V sources, 64-key chunks ----------------
// out[b,i,h,:] = 0.5*(softmax0 @ V0 + softmax1 @ V1), row-masked. 4 q rows/warp, 2 keys/lane.
__global__ __launch_bounds__(256) void attn2_kernel(
    const float* __restrict__ Q,
    const float* __restrict__ K0, const float* __restrict__ V0,
    const int* __restrict__ mc0, int Gk0,
    const float* __restrict__ K1, const float* __restrict__ V1,
    const int* __restrict__ mc1, int Gk1,
    const int* __restrict__ mrow, float* __restrict__ out, int Gq)
{
    const int b = blockIdx.z, h = blockIdx.y;
    const int warp = threadIdx.x >> 5, lane = threadIdx.x & 31;
    const int qtile = blockIdx.x * 32;
    const int r0 = warp * 4;

    __shared__ float Qs[32][68];
    __shared__ float Ks[64][68];
    __shared__ float Vs[64][68];
    __shared__ int   mcs[64];

    for (int t = threadIdx.x; t < 512; t += 256) {
        int r = t >> 4, c4 = (t & 15) * 4;
        *(float4*)&Qs[r][c4] = *(const float4*)(Q + ((long)(b*Gq + qtile + r) * HID) + h*HD + c4);
    }
    int mr[4];
    #pragma unroll
    for (int r = 0; r < 4; r++) mr[r] = mrow[b*Gq + qtile + r0 + r];

    float res0[4] = {0.f,0.f,0.f,0.f}, res1[4] = {0.f,0.f,0.f,0.f};

    #pragma unroll
    for (int s = 0; s < 2; s++) {
        const float* Kc = s ? K1 : K0;
        const float* Vc = s ? V1 : V0;
        const int*   mc = s ? mc1 : mc0;
        const int    Gk = s ? Gk1 : Gk0;

        float mmax[4], lsum[4], a0[4], a1[4];
        #pragma unroll
        for (int r = 0; r < 4; r++) { mmax[r] = -1e30f; lsum[r] = 0.f; a0[r] = 0.f; a1[r] = 0.f; }

        for (int j0 = 0; j0 < Gk; j0 += 64) {
            __syncthreads();
            for (int t = threadIdx.x; t < 1024; t += 256) {
                int r = t >> 4, c4 = (t & 15) * 4;
                long base = ((long)(b*Gk + j0 + r) * HID) + h*HD + c4;
                *(float4*)&Ks[r][c4] = *(const float4*)(Kc + base);
                *(float4*)&Vs[r][c4] = *(const float4*)(Vc + base);
            }
            if (threadIdx.x < 64) mcs[threadIdx.x] = mc[b*Gk + j0 + threadIdx.x];
            __syncthreads();

            float lgA[4] = {0.f,0.f,0.f,0.f}, lgB[4] = {0.f,0.f,0.f,0.f};
            #pragma unroll
            for (int d4 = 0; d4 < HD; d4 += 4) {
                float4 kA = *(const float4*)&Ks[lane][d4];
                float4 kB = *(const float4*)&Ks[lane + 32][d4];
                #pragma unroll
                for (int r = 0; r < 4; r++) {
                    float4 qv = *(const float4*)&Qs[r0 + r][d4];
                    lgA[r] += qv.x*kA.x + qv.y*kA.y + qv.z*kA.z + qv.w*kA.w;
                    lgB[r] += qv.x*kB.x + qv.y*kB.y + qv.z*kB.z + qv.w*kB.w;
                }
            }
            const int mA = mcs[lane], mB = mcs[lane + 32];
            float pA[4], pB[4];
            #pragma unroll
            for (int r = 0; r < 4; r++) {
                float la = (mr[r] && mA) ? lgA[r] : lgA[r] - INFV;   // exact reference semantics
                float lb = (mr[r] && mB) ? lgB[r] : lgB[r] - INFV;
                float cm = fmaxf(la, lb);
                #pragma unroll
                for (int o = 16; o; o >>= 1) cm = fmaxf(cm, __shfl_xor_sync(0xffffffffu, cm, o));
                float mnew = fmaxf(mmax[r], cm);
                float sc   = __expf(mmax[r] - mnew);
                pA[r] = __expf(la - mnew);
                pB[r] = __expf(lb - mnew);
                float ps = pA[r] + pB[r];
                #pragma unroll
                for (int o = 16; o; o >>= 1) ps += __shfl_xor_sync(0xffffffffu, ps, o);
                lsum[r] = lsum[r]*sc + ps;
                a0[r] *= sc; a1[r] *= sc;
                mmax[r] = mnew;
            }
            #pragma unroll
            for (int jj = 0; jj < 32; jj++) {
                float2 vA = *(const float2*)&Vs[jj][lane*2];
                float2 vB = *(const float2*)&Vs[jj + 32][lane*2];
                #pragma unroll
                for (int r = 0; r < 4; r++) {
                    float p0 = __shfl_sync(0xffffffffu, pA[r], jj);
                    float p1 = __shfl_sync(0xffffffffu, pB[r], jj);
                    a0[r] += p0*vA.x + p1*vB.x;
                    a1[r] += p0*vA.y + p1*vB.y;
                }
            }
        }
        #pragma unroll
        for (int r = 0; r < 4; r++) {
            float inv = 1.f / lsum[r];
            res0[r] += a0[r] * inv;
            res1[r] += a1[r] * inv;
        }
    }

    #pragma unroll
    for (int r = 0; r < 4; r++) {
        float* op = out + ((long)(b*Gq + qtile + r0 + r) * HID) + h*HD + lane*2;
        op[0] = mr[r] ? res0[r] * 0.5f : 0.f;
        op[1] = mr[r] ? res1[r] * 0.5f : 0.f;
    }
}

// ---------------- masked mean pooling + concat ----------------
__global__ void pool_kernel(const float* __restrict__ pe, const float* __restrict__ de,
                            const int* __restrict__ mp, const int* __restrict__ md,
                            float* __restrict__ x)
{
    int b = blockIdx.x, d = threadIdx.x;
    float cp = 0.f, sp = 0.f;
    for (int g = 0; g < GP; g++) {
        float m = (float)mp[b*GP + g];
        cp += m;
        sp += m * pe[((long)b*GP + g) * HID + d];
    }
    x[b*1024 + d] = sp / cp;
    float cd = 0.f, sd = 0.f;
    for (int g = 0; g < GD; g++) {
        float m = (float)md[b*GD + g];
        cd += m;
        sd += m * de[((long)b*GD + g) * HID + d];
    }
    x[b*1024 + 512 + d] = sd / cd;
}

// ---------------- MLP layer: relu(X@W+b) then train-mode BN over batch ----------------
__global__ void mlp_layer_kernel(const float* __restrict__ X, const float* __restrict__ Wm,
                                 const float* __restrict__ bias, const float* __restrict__ gamma,
                                 const float* __restrict__ beta, float* __restrict__ Y,
                                 int Kdim, int N)
{
    int n = blockIdx.x, b = threadIdx.x;
    float s = bias[n];
    for (int k = 0; k < Kdim; k++) s += X[b*Kdim + k] * Wm[(long)k*N + n];
    s = fmaxf(s, 0.f);
    float mu = s;
    #pragma unroll
    for (int o = 16; o; o >>= 1) mu += __shfl_xor_sync(0xffffffffu, mu, o);
    mu *= (1.f/32.f);
    float diff = s - mu;
    float var = diff * diff;
    #pragma unroll
    for (int o = 16; o; o >>= 1) var += __shfl_xor_sync(0xffffffffu, var, o);
    var *= (1.f/32.f);
    Y[b*N + n] = gamma[n] * diff * rsqrtf(var + EPS) + beta[n];
}

// ---------------- final: sigmoid(x3 @ wo + bo) ----------------
__global__ void final_kernel(const float* __restrict__ X3, const float* __restrict__ wo,
                             const float* __restrict__ bo, float* __restrict__ out)
{
    int b = blockIdx.x, t = threadIdx.x;
    __shared__ float red[256];
    red[t] = X3[b*256 + t] * wo[t];
    __syncthreads();
    for (int st = 128; st; st >>= 1) {
        if (t < st) red[t] += red[t + st];
        __syncthreads();
    }
    if (t == 0) out[b] = 1.f / (1.f + __expf(-(red[0] + bo[0])));
}

// ---------------- launch ----------------
static void* sym(const void* s) { void* p = nullptr; cudaGetSymbolAddress(&p, s); return p; }

extern "C" void kernel_launch(void* const* d_in, const int* in_sizes, int n_in,
                              void* d_out, int out_size)
{
    const float* prot_embed = (const float*)d_in[0];
    const float* drug_embed = (const float*)d_in[1];
    const void*  prot_mask  = d_in[2];
    const void*  drug_mask  = d_in[3];
    const float* w_preg = (const float*)d_in[4];
    const float* b_preg = (const float*)d_in[5];
    const float* w_dreg = (const float*)d_in[6];
    const float* b_dreg = (const float*)d_in[7];
    const float* wqp = (const float*)d_in[8];
    const float* wkp = (const float*)d_in[9];
    const float* wvp = (const float*)d_in[10];
    const float* wqd = (const float*)d_in[11];
    const float* wkd = (const float*)d_in[12];
    const float* wvd = (const float*)d_in[13];
    const float* w1  = (const float*)d_in[14];
    const float* b1  = (const float*)d_in[15];
    const float* g1  = (const float*)d_in[16];
    const float* be1 = (const float*)d_in[17];
    const float* w2  = (const float*)d_in[18];
    const float* b2  = (const float*)d_in[19];
    const float* g2  = (const float*)d_in[20];
    const float* be2 = (const float*)d_in[21];
    const float* w3  = (const float*)d_in[22];
    const float* b3  = (const float*)d_in[23];
    const float* g3  = (const float*)d_in[24];
    const float* be3 = (const float*)d_in[25];
    const float* wo  = (const float*)d_in[26];
    const float* bo  = (const float*)d_in[27];

    __nv_bfloat16* pgEh = (__nv_bfloat16*)sym(d_pgEh);
    __nv_bfloat16* pgEl = (__nv_bfloat16*)sym(d_pgEl);
    __nv_bfloat16* dgEh = (__nv_bfloat16*)sym(d_dgEh);
    __nv_bfloat16* dgEl = (__nv_bfloat16*)sym(d_dgEl);
    __nv_bfloat16* pgh  = (__nv_bfloat16*)sym(d_pgh);
    __nv_bfloat16* pgl  = (__nv_bfloat16*)sym(d_pgl);
    __nv_bfloat16* dgh  = (__nv_bfloat16*)sym(d_dgh);
    __nv_bfloat16* dgl  = (__nv_bfloat16*)sym(d_dgl);
    __nv_bfloat16* wpt_h = (__nv_bfloat16*)sym(d_wpt_h);
    __nv_bfloat16* wpt_l = (__nv_bfloat16*)sym(d_wpt_l);
    __nv_bfloat16* wdt_h = (__nv_bfloat16*)sym(d_wdt_h);
    __nv_bfloat16* wdt_l = (__nv_bfloat16*)sym(d_wdt_l);
    __nv_bfloat16* wqpt  = (__nv_bfloat16*)sym(d_wqp_t);
    __nv_bfloat16* wqdt  = (__nv_bfloat16*)sym(d_wqd_t);
    float* qkvp = (float*)sym(d_qkvp);
    float* qkvd = (float*)sym(d_qkvd);
    float* qp = qkvp;  float* kp = qkvp + (long)B*GP*HID;  float* vp = qkvp + 2L*B*GP*HID;
    float* qd = qkvd;  float* kd = qkvd + (long)B*GD*HID;  float* vd = qkvd + 2L*B*GD*HID;
    float* pe  = (float*)sym(d_pe);
    float* de  = (float*)sym(d_de);
    int*   mp  = (int*)  sym(d_mp);
    int*   md  = (int*)  sym(d_md);
    float* x   = (float*)sym(d_x);
    float* x1  = (float*)sym(d_x1);
    float* x2  = (float*)sym(d_x2);
    float* x3  = (float*)sym(d_x3);
    float* out = (float*)d_out;

    cudaFuncSetAttribute(gemm_wmma_kernel, cudaFuncAttributeMaxDynamicSharedMemorySize, GT_SMEM);

    const long nHK = (long)HID*HID;

    // launch 0: all 8 weight transposes + splits (tiled, coalesced)
    {
        TSJobs jobs;
        jobs.j[0] = { w_preg, wpt_h, wpt_l, DP };
        jobs.j[1] = { w_dreg, wdt_h, wdt_l, DD };
        jobs.j[2] = { wqp, wqpt + 0*nHK, wqpt + 3*nHK, HID };
        jobs.j[3] = { wkp, wqpt + 1*nHK, wqpt + 4*nHK, HID };
        jobs.j[4] = { wvp, wqpt + 2*nHK, wqpt + 5*nHK, HID };
        jobs.j[5] = { wqd, wqdt + 0*nHK, wqdt + 3*nHK, HID };
        jobs.j[6] = { wkd, wqdt + 1*nHK, wqdt + 4*nHK, HID };
        jobs.j[7] = { wvd, wqdt + 2*nHK, wqdt + 5*nHK, HID };
        transpose_all_kernel<<<dim3(DP/32, HID/32, 8), dim3(32, 8)>>>(jobs);
    }

    // launches 1,2: embedding grouping + split
    {
        long tp = (long)B*GP*(DP/4);
        group_embed_split_kernel<<<(int)((tp + 255)/256), 256>>>((const float4*)prot_embed, pgEh, pgEl, LP, DP/4);
        long td = (long)B*GD*(DD/4);
        group_embed_split_kernel<<<(int)((td + 255)/256), 256>>>((const float4*)drug_embed, dgEh, dgEl, LD, DD/4);
    }

    // launch 3 (ncu capture slot): merged projection GEMM (prot + drug), fused bias+split epilogue
    {
        GJobs jobs;
        jobs.j[0] = { pgEh, pgEl, wpt_h, wpt_h, wpt_h, wpt_l, wpt_l, wpt_l,
                      nullptr, nullptr, nullptr, b_preg, pgh, pgl, DP, (B*GP)/128 };
        jobs.j[1] = { dgEh, dgEl, wdt_h, wdt_h, wdt_h, wdt_l, wdt_l, wdt_l,
                      nullptr, nullptr, nullptr, b_dreg, dgh, dgl, DD, (B*GD)/128 };
        gemm_wmma_kernel<<<dim3(4, (B*GP)/128 + (B*GD)/128, 1), 256, GT_SMEM>>>(jobs);
    }

    // launch 4: mask dtype classification (parallel)
    detect_mask_kernel<<<1, 256>>>((const unsigned char*)prot_mask);

    // launch 5: fused mask grouping
    group_mask_all_kernel<<<(B*GP + B*GD + 255)/256, 256>>>(prot_mask, drug_mask, mp, md);

    // launch 6: merged q/k/v GEMMs (prot + drug, z = q/k/v)
    {
        GJobs jobs;
        jobs.j[0] = { pgh, pgl, wqpt + 0*nHK, wqpt + 1*nHK, wqpt + 2*nHK,
                      wqpt + 3*nHK, wqpt + 4*nHK, wqpt + 5*nHK,
                      qp, kp, vp, nullptr, nullptr, nullptr, HID, (B*GP)/128 };
        jobs.j[1] = { dgh, dgl, wqdt + 0*nHK, wqdt + 1*nHK, wqdt + 2*nHK,
                      wqdt + 3*nHK, wqdt + 4*nHK, wqdt + 5*nHK,
                      qd, kd, vd, nullptr, nullptr, nullptr, HID, (B*GD)/128 };
        gemm_wmma_kernel<<<dim3(4, (B*GP)/128 + (B*GD)/128, 3), 256, GT_SMEM>>>(jobs);
    }

    // launches 7,8: merged cross attention
    attn2_kernel<<<dim3(GP/32, NH, B), 256>>>(qp, kp, vp, mp, GP, kd, vd, md, GD, mp, pe, GP);
    attn2_kernel<<<dim3(GD/32, NH, B), 256>>>(qd, kp, vp, mp, GP, kd, vd, md, GD, md, de, GD);

    // pooling + MLP + head
    pool_kernel<<<B, 512>>>(pe, de, mp, md, x);
    mlp_layer_kernel<<<1024, 32>>>(x,  w1, b1, g1, be1, x1, 1024, 1024);
    mlp_layer_kernel<<<512,  32>>>(x1, w2, b2, g2, be2, x2, 1024, 512);
    mlp_layer_kernel<<<256,  32>>>(x2, w3, b3, g3, be3, x3, 512,  256);
    final_kernel<<<B, 256>>>(x3, wo, bo, out);

    (void)in_sizes; (void)n_in; (void)out_size;
}

// round 15
// speedup vs baseline: 3.1249x; 1.1273x over previous
#include <cuda_runtime.h>
#include <cuda_bf16.h>
#include <mma.h>
#include <math.h>
#include <stdint.h>

using namespace nvcuda;

// ---------------- problem constants ----------------
#define B   32
#define LP  2048
#define LD  512
#define DP  1280
#define DD  768
#define GP  (LP/8)      // 256
#define GD  (LD/8)      // 64
#define HID 512
#define NH  8
#define HD  64
#define INFV 1e6f
#define EPS 1e-5f

// ---------------- device scratch (static; no allocs) ----------------
__device__ __nv_bfloat16 d_pgEh[B*GP*DP], d_pgEl[B*GP*DP];
__device__ __nv_bfloat16 d_dgEh[B*GD*DD], d_dgEl[B*GD*DD];
__device__ __nv_bfloat16 d_pgh [B*GP*HID], d_pgl [B*GP*HID];
__device__ __nv_bfloat16 d_dgh [B*GD*HID], d_dgl [B*GD*HID];
__device__ __nv_bfloat16 d_wpt_h[HID*DP],  d_wpt_l[HID*DP];
__device__ __nv_bfloat16 d_wdt_h[HID*DD],  d_wdt_l[HID*DD];
__device__ __nv_bfloat16 d_wqp_t[2][3][HID*HID];
__device__ __nv_bfloat16 d_wqd_t[2][3][HID*HID];
__device__ float d_qkvp[3][B*GP*HID];
__device__ float d_qkvd[3][B*GD*HID];
__device__ float d_pe [B*GP*HID];
__device__ float d_de [B*GD*HID];
__device__ int   d_mp [B*GP];
__device__ int   d_md [B*GD];
__device__ float d_x  [B*1024];
__device__ float d_x1 [B*1024];
__device__ float d_x2 [B*512];
__device__ float d_x3 [B*256];
__device__ int   d_mask_layout;

// ---------------- small helpers ----------------
__device__ __forceinline__ void bsplit(float x, __nv_bfloat16& h, __nv_bfloat16& l) {
    h = __float2bfloat16(x);
    l = __float2bfloat16(x - __bfloat162float(h));
}
__device__ __forceinline__ void cpa16(uint32_t daddr, const void* g) {
    asm volatile("cp.async.cg.shared.global [%0], [%1], 16;" :: "r"(daddr), "l"(g));
}

// ---------------- mask layout detection (parallel; 256 threads x 16B) ----------------
__global__ void detect_mask_kernel(const unsigned char* __restrict__ m) {
    __shared__ int fu8, ff32;
    if (threadIdx.x == 0) { fu8 = 0; ff32 = 0; }
    __syncthreads();
    int u8 = 0, f32 = 0;
    const int base = threadIdx.x * 16;
    #pragma unroll
    for (int i = base; i < base + 16; i++) {
        unsigned char v = m[i];
        int r = i & 3;
        if (r != 0 && v != 0) { if (v == 1) u8 = 1; else f32 = 1; }
    }
    if (u8)  atomicOr(&fu8, 1);
    if (f32) atomicOr(&ff32, 1);
    __syncthreads();
    if (threadIdx.x == 0) d_mask_layout = fu8 ? 1 : (ff32 ? 2 : 0);
}
__device__ __forceinline__ int read_mask(const void* m, int idx, int layout) {
    if (layout == 0) return ((const int*)m)[idx] != 0;
    if (layout == 1) return ((const unsigned char*)m)[idx] != 0;
    return ((const float*)m)[idx] != 0.0f;
}

// ---------------- fused mask grouping (prot + drug in one launch) ----------------
__global__ void group_mask_all_kernel(const void* __restrict__ mP, const void* __restrict__ mD,
                                      int* __restrict__ mp, int* __restrict__ md) {
    int idx = blockIdx.x * blockDim.x + threadIdx.x;
    int layout = d_mask_layout;
    if (idx < B*GP) {
        int g = idx % GP, b = idx / GP;
        int any = 0;
        #pragma unroll
        for (int r = 0; r < 8; r++) any |= read_mask(mP, b*LP + g*8 + r, layout);
        mp[idx] = any;
    } else if (idx < B*GP + B*GD) {
        int j = idx - B*GP;
        int g = j % GD, b = j / GD;
        int any = 0;
        #pragma unroll
        for (int r = 0; r < 8; r++) any |= read_mask(mD, b*LD + g*8 + r, layout);
        md[j] = any;
    }
}

// ---------------- grouping: mean over 8 rows -> bf16 hi/lo split (HBM-roof, keep) ----------------
__global__ void group_embed_split_kernel(const float4* __restrict__ X,
                                         __nv_bfloat16* __restrict__ Yh,
                                         __nv_bfloat16* __restrict__ Yl,
                                         int L, int D4) {
    long idx = (long)blockIdx.x * blockDim.x + threadIdx.x;
    long total = (long)B * (L/8) * D4;
    if (idx >= total) return;
    int d   = (int)(idx % D4);
    long bg = idx / D4;
    int g  = (int)(bg % (L/8));
    int b  = (int)(bg / (L/8));
    const float4* p = X + ((long)b*L + (long)g*8) * D4 + d;
    float sx=0.f, sy=0.f, sz=0.f, sw=0.f;
    #pragma unroll
    for (int r = 0; r < 8; r++) {
        float4 v = p[(long)r*D4];
        sx += v.x; sy += v.y; sz += v.z; sw += v.w;
    }
    __nv_bfloat16 h0,l0,h1,l1,h2,l2,h3,l3;
    bsplit(sx*0.125f, h0, l0); bsplit(sy*0.125f, h1, l1);
    bsplit(sz*0.125f, h2, l2); bsplit(sw*0.125f, h3, l3);
    __nv_bfloat162* yh = (__nv_bfloat162*)Yh;
    __nv_bfloat162* yl = (__nv_bfloat162*)Yl;
    yh[idx*2+0] = __nv_bfloat162(h0, h1); yh[idx*2+1] = __nv_bfloat162(h2, h3);
    yl[idx*2+0] = __nv_bfloat162(l0, l1); yl[idx*2+1] = __nv_bfloat162(l2, l3);
}

// ---------------- smem-tiled weight transpose + bf16 split (8 jobs, one launch) ----------------
struct TSJob  { const float* W; __nv_bfloat16 *Th, *Tl; int K; };
struct TSJobs { TSJob j[8]; };
__global__ void transpose_all_kernel(TSJobs jobs) {
    TSJob jb = jobs.j[blockIdx.z];
    int k0 = blockIdx.x * 32, n0 = blockIdx.y * 32;
    if (k0 >= jb.K) return;
    __shared__ __nv_bfloat16 th[32][33], tl[32][33];
    int tx = threadIdx.x, ty = threadIdx.y;   // (32, 8)
    #pragma unroll
    for (int i = 0; i < 4; i++) {
        int kk = ty + i*8;
        float v = jb.W[(long)(k0 + kk) * HID + n0 + tx];   // coalesced (n fast)
        bsplit(v, th[kk][tx], tl[kk][tx]);
    }
    __syncthreads();
    #pragma unroll
    for (int i = 0; i < 4; i++) {
        int nn = ty + i*8;
        long o = (long)(n0 + nn) * jb.K + k0 + tx;          // coalesced (k fast)
        jb.Th[o] = th[tx][nn];
        jb.Tl[o] = tl[tx][nn];
    }
}

// ---------------- wmma GEMM, cp.async double-buffered, job-batched, 2 CTAs/SM ----------------
// C[M,512] = A[M,K] @ T[512,K]^T ; compensated bf16: Ah*Bh + Al*Bh + Ah*Bl.
// 128x128 CTA tile; 8 warps (warp tile 32x64); K in 32-chunks, 2-deep pipeline.
// __launch_bounds__(256,2): cap regs at 128 so 2 CTAs/SM fit (was 134 regs -> 1 CTA,
// occ 12.5%, tensor 38% — latency-bound).
#define GT_PAD 40
#define GT_ARR (128*GT_PAD)
#define GT_BUF (4*GT_ARR)
#define GT_SMEM (2*GT_BUF*2)
struct GJob {
    const __nv_bfloat16 *Ah, *Al;
    const __nv_bfloat16 *Wh0, *Wh1, *Wh2, *Wl0, *Wl1, *Wl2;
    float *C0, *C1, *C2;
    const float* bias;
    __nv_bfloat16 *Yh, *Yl;
    int K, tiles;
};
struct GJobs { GJob j[2]; };
__global__ __launch_bounds__(256, 2) void gemm_wmma_kernel(GJobs jobs) {
    extern __shared__ __nv_bfloat16 smem[];
    int yt = blockIdx.y;
    GJob jb = jobs.j[0];
    if (yt >= jb.tiles) { yt -= jb.tiles; jb = jobs.j[1]; }

    const __nv_bfloat16* Wh = (blockIdx.z == 0) ? jb.Wh0 : (blockIdx.z == 1) ? jb.Wh1 : jb.Wh2;
    const __nv_bfloat16* Wl = (blockIdx.z == 0) ? jb.Wl0 : (blockIdx.z == 1) ? jb.Wl1 : jb.Wl2;
    float* C                = (blockIdx.z == 0) ? jb.C0  : (blockIdx.z == 1) ? jb.C1  : jb.C2;
    const __nv_bfloat16* Ahi = jb.Ah;
    const __nv_bfloat16* Alo = jb.Al;
    const int K = jb.K;

    const int tid  = threadIdx.x;
    const int warp = tid >> 5;
    const int lane = tid & 31;
    const int wm   = warp & 3;
    const int wn   = warp >> 2;
    const int rowBase = yt * 128, nBase = blockIdx.x * 128;
    const int nCh = K >> 5;

    wmma::fragment<wmma::accumulator, 16, 16, 16, float> acc[2][4];
    #pragma unroll
    for (int mi = 0; mi < 2; mi++)
        #pragma unroll
        for (int ni = 0; ni < 4; ni++) wmma::fill_fragment(acc[mi][ni], 0.f);

    auto stage = [&](int ch, int buf) {
        const int k0 = ch << 5;
        __nv_bfloat16* s = smem + buf * GT_BUF;
        for (int u = tid; u < 512; u += 256) {
            int r = u >> 2, c8 = (u & 3) << 3;
            long ga = (long)(rowBase + r) * K + k0 + c8;
            long gb = (long)(nBase   + r) * K + k0 + c8;
            uint32_t d0 = (uint32_t)__cvta_generic_to_shared(s + r*GT_PAD + c8);
            cpa16(d0,            Ahi + ga);
            cpa16(d0 + 2*GT_ARR, Alo + ga);
            cpa16(d0 + 4*GT_ARR, Wh  + gb);
            cpa16(d0 + 6*GT_ARR, Wl  + gb);
        }
    };

    stage(0, 0);
    asm volatile("cp.async.commit_group;" ::: "memory");

    for (int ch = 0; ch < nCh; ch++) {
        const int buf = ch & 1;
        if (ch + 1 < nCh) {
            stage(ch + 1, 1 - buf);
            asm volatile("cp.async.commit_group;" ::: "memory");
            asm volatile("cp.async.wait_group 1;" ::: "memory");
        } else {
            asm volatile("cp.async.wait_group 0;" ::: "memory");
        }
        __syncthreads();

        const __nv_bfloat16* sAh = smem + buf*GT_BUF;
        const __nv_bfloat16* sAl = sAh + GT_ARR;
        const __nv_bfloat16* sBh = sAh + 2*GT_ARR;
        const __nv_bfloat16* sBl = sAh + 3*GT_ARR;

        #pragma unroll
        for (int ks = 0; ks < 2; ks++) {
            wmma::fragment<wmma::matrix_a, 16, 16, 16, __nv_bfloat16, wmma::row_major> a_h[2], a_l[2];
            #pragma unroll
            for (int mi = 0; mi < 2; mi++) {
                int r = (wm*32 + mi*16) * GT_PAD + ks*16;
                wmma::load_matrix_sync(a_h[mi], sAh + r, GT_PAD);
                wmma::load_matrix_sync(a_l[mi], sAl + r, GT_PAD);
            }
            #pragma unroll
            for (int ni = 0; ni < 4; ni++) {
                wmma::fragment<wmma::matrix_b, 16, 16, 16, __nv_bfloat16, wmma::col_major> b_h, b_l;
                int r = (wn*64 + ni*16) * GT_PAD + ks*16;
                wmma::load_matrix_sync(b_h, sBh + r, GT_PAD);
                wmma::load_matrix_sync(b_l, sBl + r, GT_PAD);
                #pragma unroll
                for (int mi = 0; mi < 2; mi++) {
                    wmma::mma_sync(acc[mi][ni], a_h[mi], b_h, acc[mi][ni]);
                    wmma::mma_sync(acc[mi][ni], a_l[mi], b_h, acc[mi][ni]);
                    wmma::mma_sync(acc[mi][ni], a_h[mi], b_l, acc[mi][ni]);
                }
            }
        }
        __syncthreads();
    }

    if (jb.Yh == nullptr) {
        // fp32 output (qkv GEMMs)
        #pragma unroll
        for (int mi = 0; mi < 2; mi++)
            #pragma unroll
            for (int ni = 0; ni < 4; ni++) {
                long off = (long)(rowBase + wm*32 + mi*16) * HID + nBase + wn*64 + ni*16;
                wmma::store_matrix_sync(C + off, acc[mi][ni], HID, wmma::mem_row_major);
            }
    } else {
        // fused bias + bf16 hi/lo split (projection GEMM); warp-private smem roundtrip
        float* fs = (float*)smem + warp * 320;   // 16x20 fp32 tile per warp
        #pragma unroll
        for (int mi = 0; mi < 2; mi++)
            #pragma unroll
            for (int ni = 0; ni < 4; ni++) {
                wmma::store_matrix_sync(fs, acc[mi][ni], 20, wmma::mem_row_major);
                __syncwarp();
                int row0 = rowBase + wm*32 + mi*16;
                int col0 = nBase + wn*64 + ni*16;
                #pragma unroll
                for (int e = lane; e < 256; e += 32) {
                    int r = e >> 4, c = e & 15;
                    float v = fs[r*20 + c] + jb.bias[col0 + c];
                    __nv_bfloat16 h, l; bsplit(v, h, l);
                    long o = (long)(row0 + r) * HID + col0 + c;
                    jb.Yh[o] = h; jb.Yl[o] = l;
                }
                __syncwarp();
            }
    }
}

// ---------------- merged masked attention: both K/V sources, 64-key chunks ----------------
// out[b,i,h,:] = 0.5*(softmax0 @ V0 + softmax1 @ V1), row-masked. 4 q rows/warp.
// P broadcast via per-warp smem strip + float4 reads (replaces 256 shfl/chunk).
// Dynamic smem: Qs(32x68) Ks(64x68) Vs(64x68) Ps(8x4x64) mcs(64) = 51968 B.
#define AT_SMEM (( (32*68 + 64*68 + 64*68 + 8*4*64) * 4 ) + 64*4)
__global__ __launch_bounds__(256) void attn2_kernel(
    const float* __restrict__ Q,
    const float* __restrict__ K0, const float* __restrict__ V0,
    const int* __restrict__ mc0, int Gk0,
    const float* __restrict__ K1, const float* __restrict__ V1,
    const int* __restrict__ mc1, int Gk1,
    const int* __restrict__ mrow, float* __restrict__ out, int Gq)
{
    extern __shared__ float asm_f[];
    float (*Qs)[68] = (float(*)[68])asm_f;                       // 32x68
    float (*Ks)[68] = (float(*)[68])(asm_f + 32*68);             // 64x68
    float (*Vs)[68] = (float(*)[68])(asm_f + 32*68 + 64*68);     // 64x68
    float* Ps       = asm_f + 32*68 + 2*64*68;                   // 8 warps x 4 rows x 64
    int*   mcs      = (int*)(Ps + 8*4*64);                       // 64

    const int b = blockIdx.z, h = blockIdx.y;
    const int warp = threadIdx.x >> 5, lane = threadIdx.x & 31;
    const int qtile = blockIdx.x * 32;
    const int r0 = warp * 4;
    float* Pw = Ps + warp * 256;                                  // this warp's 4x64 strip

    for (int t = threadIdx.x; t < 512; t += 256) {
        int r = t >> 4, c4 = (t & 15) * 4;
        *(float4*)&Qs[r][c4] = *(const float4*)(Q + ((long)(b*Gq + qtile + r) * HID) + h*HD + c4);
    }
    int mr[4];
    #pragma unroll
    for (int r = 0; r < 4; r++) mr[r] = mrow[b*Gq + qtile + r0 + r];

    float res0[4] = {0.f,0.f,0.f,0.f}, res1[4] = {0.f,0.f,0.f,0.f};

    #pragma unroll
    for (int s = 0; s < 2; s++) {
        const float* Kc = s ? K1 : K0;
        const float* Vc = s ? V1 : V0;
        const int*   mc = s ? mc1 : mc0;
        const int    Gk = s ? Gk1 : Gk0;

        float mmax[4], lsum[4], a0[4], a1[4];
        #pragma unroll
        for (int r = 0; r < 4; r++) { mmax[r] = -1e30f; lsum[r] = 0.f; a0[r] = 0.f; a1[r] = 0.f; }

        for (int j0 = 0; j0 < Gk; j0 += 64) {
            __syncthreads();
            for (int t = threadIdx.x; t < 1024; t += 256) {
                int r = t >> 4, c4 = (t & 15) * 4;
                long base = ((long)(b*Gk + j0 + r) * HID) + h*HD + c4;
                *(float4*)&Ks[r][c4] = *(const float4*)(Kc + base);
                *(float4*)&Vs[r][c4] = *(const float4*)(Vc + base);
            }
            if (threadIdx.x < 64) mcs[threadIdx.x] = mc[b*Gk + j0 + threadIdx.x];
            __syncthreads();

            float lgA[4] = {0.f,0.f,0.f,0.f}, lgB[4] = {0.f,0.f,0.f,0.f};
            #pragma unroll
            for (int d4 = 0; d4 < HD; d4 += 4) {
                float4 kA = *(const float4*)&Ks[lane][d4];
                float4 kB = *(const float4*)&Ks[lane + 32][d4];
                #pragma unroll
                for (int r = 0; r < 4; r++) {
                    float4 qv = *(const float4*)&Qs[r0 + r][d4];
                    lgA[r] += qv.x*kA.x + qv.y*kA.y + qv.z*kA.z + qv.w*kA.w;
                    lgB[r] += qv.x*kB.x + qv.y*kB.y + qv.z*kB.z + qv.w*kB.w;
                }
            }
            const int mA = mcs[lane], mB = mcs[lane + 32];
            #pragma unroll
            for (int r = 0; r < 4; r++) {
                float la = (mr[r] && mA) ? lgA[r] : lgA[r] - INFV;   // exact reference semantics
                float lb = (mr[r] && mB) ? lgB[r] : lgB[r] - INFV;
                float cm = fmaxf(la, lb);
                #pragma unroll
                for (int o = 16; o; o >>= 1) cm = fmaxf(cm, __shfl_xor_sync(0xffffffffu, cm, o));
                float mnew = fmaxf(mmax[r], cm);
                float sc   = __expf(mmax[r] - mnew);
                float pA = __expf(la - mnew);
                float pB = __expf(lb - mnew);
                Pw[r*64 + lane]      = pA;
                Pw[r*64 + lane + 32] = pB;
                float ps = pA + pB;
                #pragma unroll
                for (int o = 16; o; o >>= 1) ps += __shfl_xor_sync(0xffffffffu, ps, o);
                lsum[r] = lsum[r]*sc + ps;
                a0[r] *= sc; a1[r] *= sc;
                mmax[r] = mnew;
            }
            __syncwarp();
            #pragma unroll
            for (int jj = 0; jj < 64; jj += 4) {
                float2 v0 = *(const float2*)&Vs[jj+0][lane*2];
                float2 v1 = *(const float2*)&Vs[jj+1][lane*2];
                float2 v2 = *(const float2*)&Vs[jj+2][lane*2];
                float2 v3 = *(const float2*)&Vs[jj+3][lane*2];
                #pragma unroll
                for (int r = 0; r < 4; r++) {
                    float4 p = *(const float4*)&Pw[r*64 + jj];   // warp-uniform broadcast
                    a0[r] += p.x*v0.x + p.y*v1.x + p.z*v2.x + p.w*v3.x;
                    a1[r] += p.x*v0.y + p.y*v1.y + p.z*v2.y + p.w*v3.y;
                }
            }
            __syncwarp();
        }
        #pragma unroll
        for (int r = 0; r < 4; r++) {
            float inv = 1.f / lsum[r];
            res0[r] += a0[r] * inv;
            res1[r] += a1[r] * inv;
        }
    }

    #pragma unroll
    for (int r = 0; r < 4; r++) {
        float* op = out + ((long)(b*Gq + qtile + r0 + r) * HID) + h*HD + lane*2;
        op[0] = mr[r] ? res0[r] * 0.5f : 0.f;
        op[1] = mr[r] ? res1[r] * 0.5f : 0.f;
    }
}

// ---------------- masked mean pooling + concat ----------------
__global__ void pool_kernel(const float* __restrict__ pe, const float* __restrict__ de,
                            const int* __restrict__ mp, const int* __restrict__ md,
                            float* __restrict__ x)
{
    int b = blockIdx.x, d = threadIdx.x;
    float cp = 0.f, sp = 0.f;
    for (int g = 0; g < GP; g++) {
        float m = (float)mp[b*GP + g];
        cp += m;
        sp += m * pe[((long)b*GP + g) * HID + d];
    }
    x[b*1024 + d] = sp / cp;
    float cd = 0.f, sd = 0.f;
    for (int g = 0; g < GD; g++) {
        float m = (float)md[b*GD + g];
        cd += m;
        sd += m * de[((long)b*GD + g) * HID + d];
    }
    x[b*1024 + 512 + d] = sd / cd;
}

// ---------------- MLP layer: relu(X@W+b) then train-mode BN over batch ----------------
__global__ void mlp_layer_kernel(const float* __restrict__ X, const float* __restrict__ Wm,
                                 const float* __restrict__ bias, const float* __restrict__ gamma,
                                 const float* __restrict__ beta, float* __restrict__ Y,
                                 int Kdim, int N)
{
    int n = blockIdx.x, b = threadIdx.x;
    float s = bias[n];
    for (int k = 0; k < Kdim; k++) s += X[b*Kdim + k] * Wm[(long)k*N + n];
    s = fmaxf(s, 0.f);
    float mu = s;
    #pragma unroll
    for (int o = 16; o; o >>= 1) mu += __shfl_xor_sync(0xffffffffu, mu, o);
    mu *= (1.f/32.f);
    float diff = s - mu;
    float var = diff * diff;
    #pragma unroll
    for (int o = 16; o; o >>= 1) var += __shfl_xor_sync(0xffffffffu, var, o);
    var *= (1.f/32.f);
    Y[b*N + n] = gamma[n] * diff * rsqrtf(var + EPS) + beta[n];
}

// ---------------- final: sigmoid(x3 @ wo + bo) ----------------
__global__ void final_kernel(const float* __restrict__ X3, const float* __restrict__ wo,
                             const float* __restrict__ bo, float* __restrict__ out)
{
    int b = blockIdx.x, t = threadIdx.x;
    __shared__ float red[256];
    red[t] = X3[b*256 + t] * wo[t];
    __syncthreads();
    for (int st = 128; st; st >>= 1) {
        if (t < st) red[t] += red[t + st];
        __syncthreads();
    }
    if (t == 0) out[b] = 1.f / (1.f + __expf(-(red[0] + bo[0])));
}

// ---------------- launch ----------------
static void* sym(const void* s) { void* p = nullptr; cudaGetSymbolAddress(&p, s); return p; }

extern "C" void kernel_launch(void* const* d_in, const int* in_sizes, int n_in,
                              void* d_out, int out_size)
{
    const float* prot_embed = (const float*)d_in[0];
    const float* drug_embed = (const float*)d_in[1];
    const void*  prot_mask  = d_in[2];
    const void*  drug_mask  = d_in[3];
    const float* w_preg = (const float*)d_in[4];
    const float* b_preg = (const float*)d_in[5];
    const float* w_dreg = (const float*)d_in[6];
    const float* b_dreg = (const float*)d_in[7];
    const float* wqp = (const float*)d_in[8];
    const float* wkp = (const float*)d_in[9];
    const float* wvp = (const float*)d_in[10];
    const float* wqd = (const float*)d_in[11];
    const float* wkd = (const float*)d_in[12];
    const float* wvd = (const float*)d_in[13];
    const float* w1  = (const float*)d_in[14];
    const float* b1  = (const float*)d_in[15];
    const float* g1  = (const float*)d_in[16];
    const float* be1 = (const float*)d_in[17];
    const float* w2  = (const float*)d_in[18];
    const float* b2  = (const float*)d_in[19];
    const float* g2  = (const float*)d_in[20];
    const float* be2 = (const float*)d_in[21];
    const float* w3  = (const float*)d_in[22];
    const float* b3  = (const float*)d_in[23];
    const float* g3  = (const float*)d_in[24];
    const float* be3 = (const float*)d_in[25];
    const float* wo  = (const float*)d_in[26];
    const float* bo  = (const float*)d_in[27];

    __nv_bfloat16* pgEh = (__nv_bfloat16*)sym(d_pgEh);
    __nv_bfloat16* pgEl = (__nv_bfloat16*)sym(d_pgEl);
    __nv_bfloat16* dgEh = (__nv_bfloat16*)sym(d_dgEh);
    __nv_bfloat16* dgEl = (__nv_bfloat16*)sym(d_dgEl);
    __nv_bfloat16* pgh  = (__nv_bfloat16*)sym(d_pgh);
    __nv_bfloat16* pgl  = (__nv_bfloat16*)sym(d_pgl);
    __nv_bfloat16* dgh  = (__nv_bfloat16*)sym(d_dgh);
    __nv_bfloat16* dgl  = (__nv_bfloat16*)sym(d_dgl);
    __nv_bfloat16* wpt_h = (__nv_bfloat16*)sym(d_wpt_h);
    __nv_bfloat16* wpt_l = (__nv_bfloat16*)sym(d_wpt_l);
    __nv_bfloat16* wdt_h = (__nv_bfloat16*)sym(d_wdt_h);
    __nv_bfloat16* wdt_l = (__nv_bfloat16*)sym(d_wdt_l);
    __nv_bfloat16* wqpt  = (__nv_bfloat16*)sym(d_wqp_t);
    __nv_bfloat16* wqdt  = (__nv_bfloat16*)sym(d_wqd_t);
    float* qkvp = (float*)sym(d_qkvp);
    float* qkvd = (float*)sym(d_qkvd);
    float* qp = qkvp;  float* kp = qkvp + (long)B*GP*HID;  float* vp = qkvp + 2L*B*GP*HID;
    float* qd = qkvd;  float* kd = qkvd + (long)B*GD*HID;  float* vd = qkvd + 2L*B*GD*HID;
    float* pe  = (float*)sym(d_pe);
    float* de  = (float*)sym(d_de);
    int*   mp  = (int*)  sym(d_mp);
    int*   md  = (int*)  sym(d_md);
    float* x   = (float*)sym(d_x);
    float* x1  = (float*)sym(d_x1);
    float* x2  = (float*)sym(d_x2);
    float* x3  = (float*)sym(d_x3);
    float* out = (float*)d_out;

    cudaFuncSetAttribute(gemm_wmma_kernel, cudaFuncAttributeMaxDynamicSharedMemorySize, GT_SMEM);
    cudaFuncSetAttribute(attn2_kernel,     cudaFuncAttributeMaxDynamicSharedMemorySize, AT_SMEM);

    const long nHK = (long)HID*HID;

    // launch 0: all 8 weight transposes + splits (tiled, coalesced)
    {
        TSJobs jobs;
        jobs.j[0] = { w_preg, wpt_h, wpt_l, DP };
        jobs.j[1] = { w_dreg, wdt_h, wdt_l, DD };
        jobs.j[2] = { wqp, wqpt + 0*nHK, wqpt + 3*nHK, HID };
        jobs.j[3] = { wkp, wqpt + 1*nHK, wqpt + 4*nHK, HID };
        jobs.j[4] = { wvp, wqpt + 2*nHK, wqpt + 5*nHK, HID };
        jobs.j[5] = { wqd, wqdt + 0*nHK, wqdt + 3*nHK, HID };
        jobs.j[6] = { wkd, wqdt + 1*nHK, wqdt + 4*nHK, HID };
        jobs.j[7] = { wvd, wqdt + 2*nHK, wqdt + 5*nHK, HID };
        transpose_all_kernel<<<dim3(DP/32, HID/32, 8), dim3(32, 8)>>>(jobs);
    }

    // launches 1,2: embedding grouping + split
    {
        long tp = (long)B*GP*(DP/4);
        group_embed_split_kernel<<<(int)((tp + 255)/256), 256>>>((const float4*)prot_embed, pgEh, pgEl, LP, DP/4);
        long td = (long)B*GD*(DD/4);
        group_embed_split_kernel<<<(int)((td + 255)/256), 256>>>((const float4*)drug_embed, dgEh, dgEl, LD, DD/4);
    }

    // launch 3 (ncu capture slot): merged projection GEMM (prot + drug), fused bias+split epilogue
    {
        GJobs jobs;
        jobs.j[0] = { pgEh, pgEl, wpt_h, wpt_h, wpt_h, wpt_l, wpt_l, wpt_l,
                      nullptr, nullptr, nullptr, b_preg, pgh, pgl, DP, (B*GP)/128 };
        jobs.j[1] = { dgEh, dgEl, wdt_h, wdt_h, wdt_h, wdt_l, wdt_l, wdt_l,
                      nullptr, nullptr, nullptr, b_dreg, dgh, dgl, DD, (B*GD)/128 };
        gemm_wmma_kernel<<<dim3(4, (B*GP)/128 + (B*GD)/128, 1), 256, GT_SMEM>>>(jobs);
    }

    // launch 4: mask dtype classification (parallel)
    detect_mask_kernel<<<1, 256>>>((const unsigned char*)prot_mask);

    // launch 5: fused mask grouping
    group_mask_all_kernel<<<(B*GP + B*GD + 255)/256, 256>>>(prot_mask, drug_mask, mp, md);

    // launch 6: merged q/k/v GEMMs (prot + drug, z = q/k/v)
    {
        GJobs jobs;
        jobs.j[0] = { pgh, pgl, wqpt + 0*nHK, wqpt + 1*nHK, wqpt + 2*nHK,
                      wqpt + 3*nHK, wqpt + 4*nHK, wqpt + 5*nHK,
                      qp, kp, vp, nullptr, nullptr, nullptr, HID, (B*GP)/128 };
        jobs.j[1] = { dgh, dgl, wqdt + 0*nHK, wqdt + 1*nHK, wqdt + 2*nHK,
                      wqdt + 3*nHK, wqdt + 4*nHK, wqdt + 5*nHK,
                      qd, kd, vd, nullptr, nullptr, nullptr, HID, (B*GD)/128 };
        gemm_wmma_kernel<<<dim3(4, (B*GP)/128 + (B*GD)/128, 3), 256, GT_SMEM>>>(jobs);
    }

    // launches 7,8: merged cross attention
    attn2_kernel<<<dim3(GP/32, NH, B), 256, AT_SMEM>>>(qp, kp, vp, mp, GP, kd, vd, md, GD, mp, pe, GP);
    attn2_kernel<<<dim3(GD/32, NH, B), 256, AT_SMEM>>>(qd, kp, vp, mp, GP, kd, vd, md, GD, md, de, GD);

    // pooling + MLP + head
    pool_kernel<<<B, 512>>>(pe, de, mp, md, x);
    mlp_layer_kernel<<<1024, 32>>>(x,  w1, b1, g1, be1, x1, 1024, 1024);
    mlp_layer_kernel<<<512,  32>>>(x1, w2, b2, g2, be2, x2, 1024, 512);
    mlp_layer_kernel<<<256,  32>>>(x2, w3, b3, g3, be3, x3, 512,  256);
    final_kernel<<<B, 256>>>(x3, wo, bo, out);

    (void)in_sizes; (void)n_in; (void)out_size;
}